// round 1
// baseline (speedup 1.0000x reference)
#include <cuda_runtime.h>

#define EPS 1e-5f

// ---------------- scratch layout (floats) ----------------
static const size_t OFF_XBUF0 = 0;          // 256*4096
static const size_t OFF_PAD2  = 1048576;    // 128*130*130
static const size_t OFF_WT2   = 3211776;    // 1152*256
static const size_t OFF_G2    = 3506688;    // 256*16384
static const size_t OFF_KK1   = 7700992;    // 9*16384
static const size_t OFF_Z1    = 7848448;    // 1152*4096
static const size_t OFF_X1    = 12567040;   // 128*16384
static const size_t OFF_PAD1  = 14664192;   // 64*258*258
static const size_t OFF_WT1   = 18924288;   // 576*128
static const size_t OFF_G1    = 18998016;   // 128*65536
static const size_t OFF_KK2   = 27386624;   // 9*65536
static const size_t OFF_Z2    = 27976448;   // 576*16384
static const size_t OFF_X2    = 37413632;   // 64*65536
static const size_t SCRATCH_FLOATS = 41607936; // ~166 MB

__device__ float g_scratch[SCRATCH_FLOATS];

// ---------------- fused double instance-norm + residual (x2) ----------------
// z = m + (x-m)*a*(1+rsqrt(v*a^2+eps)),  a = 1+rsqrt(v+eps)
__global__ __launch_bounds__(256) void inorm2_kernel(const float* __restrict__ in,
                                                     float* __restrict__ out, int HW) {
    int c = blockIdx.x;
    const float* x = in + (size_t)c * HW;
    float* y = out + (size_t)c * HW;
    float s = 0.f, s2 = 0.f;
    for (int i = threadIdx.x; i < HW; i += 256) {
        float v = x[i]; s += v; s2 += v * v;
    }
    __shared__ float rs[256], rq[256];
    rs[threadIdx.x] = s; rq[threadIdx.x] = s2;
    __syncthreads();
    for (int o = 128; o > 0; o >>= 1) {
        if (threadIdx.x < o) { rs[threadIdx.x] += rs[threadIdx.x + o]; rq[threadIdx.x] += rq[threadIdx.x + o]; }
        __syncthreads();
    }
    float m = rs[0] / (float)HW;
    float v = rq[0] / (float)HW - m * m;
    if (v < 0.f) v = 0.f;
    float a = 1.f + rsqrtf(v + EPS);
    float scale = a * (1.f + rsqrtf(v * a * a + EPS));
    for (int i = threadIdx.x; i < HW; i += 256) {
        y[i] = m + (x[i] - m) * scale;
    }
}

// ---------------- zero-pad (H,W) -> (H+2,W+2) ----------------
__global__ void pad_kernel(const float* __restrict__ in, float* __restrict__ out, int H, int W) {
    int c = blockIdx.y;
    int Hp = H + 2, Wp = W + 2;
    int idx = blockIdx.x * blockDim.x + threadIdx.x;
    if (idx >= Hp * Wp) return;
    int y = idx / Wp, x = idx % Wp;
    float v = 0.f;
    if (y >= 1 && y <= H && x >= 1 && x <= W)
        v = in[((size_t)c * H + (y - 1)) * W + (x - 1)];
    out[(size_t)c * Hp * Wp + idx] = v;
}

// ---------------- weight transpose: (O,Cin,3,3) -> [k=t*Cin+c][m=o] ----------------
__global__ void wtrans_kernel(const float* __restrict__ w, float* __restrict__ wt, int O, int Cin) {
    int idx = blockIdx.x * blockDim.x + threadIdx.x;
    int total = O * Cin * 9;
    if (idx >= total) return;
    int t = idx % 9; int rest = idx / 9; int c = rest % Cin; int o = rest / Cin;
    wt[((size_t)(t * Cin + c)) * O + o] = w[idx];
}

// ---------------- generic GEMM / implicit conv GEMM ----------------
// C[m,p] = bias[m] + sum_k A[k,m] * B[c(k)*strideC + (h+di)*Wp + (w+dj)]
// k = t*Cin + c (Cin = 1<<cinShift); p -> h = p>>wShift, w = p & wmask.
// 1-tap mode: cinShift >= log2(K) so t==0, Wp = N, wShift = log2(N).
__global__ __launch_bounds__(256) void gemm_kernel(
    const float* __restrict__ A, const float* __restrict__ B,
    const float* __restrict__ bias, float* __restrict__ C,
    int M, int N, int K, int cinShift, int Wp, int wShift, int strideC)
{
    __shared__ float As[16][64];
    __shared__ float Bs[16][64];
    int tid = threadIdx.x;
    int m0 = blockIdx.y * 64;
    int p0 = blockIdx.x * 64;
    int cmask = (1 << cinShift) - 1;
    int wmask = (1 << wShift) - 1;
    float acc[4][4] = {};
    int lm = tid & 63, lk = tid >> 6;        // 64-wide loads, 4 k-rows per pass
    int row4 = (tid >> 4) << 2;
    int col4 = (tid & 15) << 2;
    int p = p0 + lm;
    int h = p >> wShift, w = p & wmask;
    for (int k0 = 0; k0 < K; k0 += 16) {
#pragma unroll
        for (int r = 0; r < 4; r++) {
            int kk = lk + r * 4;
            int k = k0 + kk;
            As[kk][lm] = A[(size_t)k * M + m0 + lm];
            int cch = k & cmask, t = k >> cinShift;
            int di = (t >= 6) ? 2 : (t >= 3 ? 1 : 0);
            int dj = t - di * 3;
            Bs[kk][lm] = B[(size_t)cch * strideC + (h + di) * Wp + (w + dj)];
        }
        __syncthreads();
#pragma unroll
        for (int kk = 0; kk < 16; kk++) {
            float4 av = *(const float4*)&As[kk][row4];
            float4 bv = *(const float4*)&Bs[kk][col4];
            float ar[4] = {av.x, av.y, av.z, av.w};
            float br[4] = {bv.x, bv.y, bv.z, bv.w};
#pragma unroll
            for (int i = 0; i < 4; i++)
#pragma unroll
                for (int j = 0; j < 4; j++)
                    acc[i][j] += ar[i] * br[j];
        }
        __syncthreads();
    }
#pragma unroll
    for (int i = 0; i < 4; i++) {
        float bv = bias ? bias[m0 + row4 + i] : 0.f;
#pragma unroll
        for (int j = 0; j < 4; j++)
            C[(size_t)(m0 + row4 + i) * N + p0 + col4 + j] = acc[i][j] + bv;
    }
}

// ---------------- guide kernel: kk[t,p] = exp(-0.5*sum_c (g_pad[nbr]-g[ctr])^2) ----------------
__global__ __launch_bounds__(256) void kk_kernel(const float* __restrict__ g,
                                                 float* __restrict__ kkout,
                                                 int C, int H, int W) {
    __shared__ float tile[4][18][18];
    int tx = threadIdx.x & 15, ty = threadIdx.x >> 4;
    int w0 = blockIdx.x * 16, h0 = blockIdx.y * 16;
    float acc[9] = {};
    int HW = H * W;
    for (int c0 = 0; c0 < C; c0 += 4) {
        __syncthreads();
        for (int idx = threadIdx.x; idx < 4 * 324; idx += 256) {
            int cc = idx / 324, rem = idx % 324;
            int yy = rem / 18, xx = rem % 18;
            int gy = h0 + yy - 1, gx = w0 + xx - 1;
            float v = 0.f;
            if (gy >= 0 && gy < H && gx >= 0 && gx < W)
                v = g[(size_t)(c0 + cc) * HW + gy * W + gx];
            tile[cc][yy][xx] = v;
        }
        __syncthreads();
#pragma unroll
        for (int cc = 0; cc < 4; cc++) {
            float ctr = tile[cc][ty + 1][tx + 1];
#pragma unroll
            for (int t = 0; t < 9; t++) {
                float d = tile[cc][ty + t / 3][tx + t % 3] - ctr;
                acc[t] += d * d;
            }
        }
    }
    int p = (h0 + ty) * W + (w0 + tx);
#pragma unroll
    for (int t = 0; t < 9; t++)
        kkout[(size_t)t * HW + p] = __expf(-0.5f * acc[t]);
}

// ---------------- PAC combine: out[o,p] = b[o] + sum_valid_t kk[t,p]*z[o*9+t, src] ----------------
__global__ void pac_combine_kernel(const float* __restrict__ z, const float* __restrict__ kkb,
                                   const float* __restrict__ bias, float* __restrict__ out,
                                   int Ho, int Wo, int Hin, int Win, int woShift) {
    int o = blockIdx.y;
    int p = blockIdx.x * blockDim.x + threadIdx.x;
    int np = Ho * Wo;
    if (p >= np) return;
    int h = p >> woShift, w = p & (Wo - 1);
    int nsrc = Hin * Win;
    float s = bias[o];
#pragma unroll
    for (int i = 0; i < 3; i++) {
        int hi = h + i;
        if (!(hi & 1)) continue;          // stride-2 parity
        int sh = (hi - 1) >> 1;
        if (sh >= Hin) continue;
#pragma unroll
        for (int j = 0; j < 3; j++) {
            int wj = w + j;
            if (!(wj & 1)) continue;
            int sw = (wj - 1) >> 1;
            if (sw >= Win) continue;
            int t = i * 3 + j;
            s += kkb[(size_t)t * np + p] * z[(size_t)(o * 9 + t) * nsrc + sh * Win + sw];
        }
    }
    out[(size_t)o * np + p] = s;
}

// ---------------- final 3x3 conv, 64 -> 3 channels, 256x256 ----------------
__global__ __launch_bounds__(256) void conv_out_kernel(const float* __restrict__ in,
                                                       const float* __restrict__ wgt,
                                                       const float* __restrict__ bias,
                                                       float* __restrict__ out) {
    __shared__ float ws[3 * 64 * 9];
    __shared__ float tile[8][18][18];
    const int H = 256, W = 256;
    for (int idx = threadIdx.x; idx < 1728; idx += 256) ws[idx] = wgt[idx];
    int tx = threadIdx.x & 15, ty = threadIdx.x >> 4;
    int w0 = blockIdx.x * 16, h0 = blockIdx.y * 16;
    float acc[3] = {bias[0], bias[1], bias[2]};
    for (int c0 = 0; c0 < 64; c0 += 8) {
        __syncthreads();
        for (int idx = threadIdx.x; idx < 8 * 324; idx += 256) {
            int cc = idx / 324, rem = idx % 324;
            int yy = rem / 18, xx = rem % 18;
            int gy = h0 + yy - 1, gx = w0 + xx - 1;
            float v = 0.f;
            if (gy >= 0 && gy < H && gx >= 0 && gx < W)
                v = in[(size_t)(c0 + cc) * H * W + gy * W + gx];
            tile[cc][yy][xx] = v;
        }
        __syncthreads();
#pragma unroll
        for (int cc = 0; cc < 8; cc++) {
            float v[9];
#pragma unroll
            for (int t = 0; t < 9; t++)
                v[t] = tile[cc][ty + t / 3][tx + t % 3];
#pragma unroll
            for (int o = 0; o < 3; o++)
#pragma unroll
                for (int t = 0; t < 9; t++)
                    acc[o] += v[t] * ws[(o * 64 + c0 + cc) * 9 + t];
        }
    }
    int p = (h0 + ty) * W + (w0 + tx);
#pragma unroll
    for (int o = 0; o < 3; o++) out[(size_t)o * H * W + p] = acc[o];
}

// ---------------- host ----------------
extern "C" void kernel_launch(void* const* d_in, const int* in_sizes, int n_in,
                              void* d_out, int out_size) {
    const float* x       = (const float*)d_in[0];
    const float* ef2     = (const float*)d_in[1];
    const float* ef1     = (const float*)d_in[2];
    const float* w_adj2  = (const float*)d_in[3];
    const float* b_adj2  = (const float*)d_in[4];
    const float* w_adj1  = (const float*)d_in[5];
    const float* b_adj1  = (const float*)d_in[6];
    const float* w_pac16 = (const float*)d_in[7];
    const float* b_pac16 = (const float*)d_in[8];
    const float* w_pac20 = (const float*)d_in[9];
    const float* b_pac20 = (const float*)d_in[10];
    const float* w_out   = (const float*)d_in[11];
    const float* b_out   = (const float*)d_in[12];
    float* out = (float*)d_out;

    float* S = nullptr;
    cudaGetSymbolAddress((void**)&S, g_scratch);
    float* xbuf0 = S + OFF_XBUF0;
    float* pad2  = S + OFF_PAD2;
    float* wt2   = S + OFF_WT2;
    float* g2    = S + OFF_G2;
    float* kk1   = S + OFF_KK1;
    float* z1    = S + OFF_Z1;
    float* x1    = S + OFF_X1;
    float* pad1  = S + OFF_PAD1;
    float* wt1   = S + OFF_WT1;
    float* g1    = S + OFF_G1;
    float* kk2   = S + OFF_KK2;
    float* z2    = S + OFF_Z2;
    float* x2    = S + OFF_X2;

    // stage 0: double inorm on x (256 ch, 64x64)
    inorm2_kernel<<<256, 256>>>(x, xbuf0, 4096);

    // guide conv g2 = conv3x3(ef_lv2; 128->256 @128x128)
    pad_kernel<<<dim3(67, 128), 256>>>(ef2, pad2, 128, 128);
    wtrans_kernel<<<(294912 + 255) / 256, 256>>>(w_adj2, wt2, 256, 128);
    gemm_kernel<<<dim3(16384 / 64, 256 / 64), 256>>>(wt2, pad2, b_adj2, g2,
                                                     256, 16384, 1152, 7, 130, 7, 16900);
    // PAC 16: kk from g2 (256 ch), z1 = W^T x, combine -> x1 (128 ch @128x128)
    kk_kernel<<<dim3(8, 8), 256>>>(g2, kk1, 256, 128, 128);
    gemm_kernel<<<dim3(4096 / 64, 1152 / 64), 256>>>(w_pac16, xbuf0, nullptr, z1,
                                                     1152, 4096, 256, 8, 4096, 12, 4096);
    pac_combine_kernel<<<dim3(64, 128), 256>>>(z1, kk1, b_pac16, x1, 128, 128, 64, 64, 7);
    inorm2_kernel<<<128, 256>>>(x1, x1, 16384);

    // guide conv g1 = conv3x3(ef_lv1; 64->128 @256x256)
    pad_kernel<<<dim3(261, 64), 256>>>(ef1, pad1, 256, 256);
    wtrans_kernel<<<(73728 + 255) / 256, 256>>>(w_adj1, wt1, 128, 64);
    gemm_kernel<<<dim3(65536 / 64, 128 / 64), 256>>>(wt1, pad1, b_adj1, g1,
                                                     128, 65536, 576, 6, 258, 8, 66564);
    // PAC 20: kk from g1 (128 ch), z2, combine -> x2 (64 ch @256x256)
    kk_kernel<<<dim3(16, 16), 256>>>(g1, kk2, 128, 256, 256);
    gemm_kernel<<<dim3(16384 / 64, 576 / 64), 256>>>(w_pac20, x1, nullptr, z2,
                                                     576, 16384, 128, 7, 16384, 14, 16384);
    pac_combine_kernel<<<dim3(256, 64), 256>>>(z2, kk2, b_pac20, x2, 256, 256, 128, 128, 8);
    inorm2_kernel<<<64, 256>>>(x2, x2, 65536);

    // final conv 64 -> 3
    conv_out_kernel<<<dim3(16, 16), 256>>>(x2, w_out, b_out, out);
}

// round 2
// speedup vs baseline: 1.0088x; 1.0088x over previous
#include <cuda_runtime.h>

#define EPS 1e-5f

// ---------------- scratch layout (floats) ----------------
static const size_t OFF_XBUF0 = 0;          // 256*4096
static const size_t OFF_PAD2  = 1048576;    // 128*130*130
static const size_t OFF_WT2   = 3211776;    // 1152*256
static const size_t OFF_G2    = 3506688;    // 256*16384
static const size_t OFF_KK1   = 7700992;    // 9*16384
static const size_t OFF_Z1    = 7848448;    // 1152*4096
static const size_t OFF_X1    = 12567040;   // 128*16384
static const size_t OFF_PAD1  = 14664192;   // 64*258*258
static const size_t OFF_WT1   = 18924288;   // 576*128
static const size_t OFF_G1    = 18998016;   // 128*65536
static const size_t OFF_KK2   = 27386624;   // 9*65536
static const size_t OFF_Z2    = 27976448;   // 576*16384
static const size_t OFF_X2    = 37413632;   // 64*65536
static const size_t SCRATCH_FLOATS = 41607936; // ~166 MB

__device__ float g_scratch[SCRATCH_FLOATS];

// ---------------- fused double instance-norm + residual (x2) ----------------
__global__ __launch_bounds__(256) void inorm2_kernel(const float* __restrict__ in,
                                                     float* __restrict__ out, int HW) {
    int c = blockIdx.x;
    const float* x = in + (size_t)c * HW;
    float* y = out + (size_t)c * HW;
    float s = 0.f, s2 = 0.f;
    for (int i = threadIdx.x; i < HW; i += 256) {
        float v = x[i]; s += v; s2 += v * v;
    }
    __shared__ float rs[256], rq[256];
    rs[threadIdx.x] = s; rq[threadIdx.x] = s2;
    __syncthreads();
    for (int o = 128; o > 0; o >>= 1) {
        if (threadIdx.x < o) { rs[threadIdx.x] += rs[threadIdx.x + o]; rq[threadIdx.x] += rq[threadIdx.x + o]; }
        __syncthreads();
    }
    float m = rs[0] / (float)HW;
    float v = rq[0] / (float)HW - m * m;
    if (v < 0.f) v = 0.f;
    float a = 1.f + rsqrtf(v + EPS);
    float scale = a * (1.f + rsqrtf(v * a * a + EPS));
    for (int i = threadIdx.x; i < HW; i += 256) {
        y[i] = m + (x[i] - m) * scale;
    }
}

// ---------------- zero-pad (H,W) -> (H+2,W+2) ----------------
__global__ void pad_kernel(const float* __restrict__ in, float* __restrict__ out, int H, int W) {
    int c = blockIdx.y;
    int Hp = H + 2, Wp = W + 2;
    int idx = blockIdx.x * blockDim.x + threadIdx.x;
    if (idx >= Hp * Wp) return;
    int y = idx / Wp, x = idx % Wp;
    float v = 0.f;
    if (y >= 1 && y <= H && x >= 1 && x <= W)
        v = in[((size_t)c * H + (y - 1)) * W + (x - 1)];
    out[(size_t)c * Hp * Wp + idx] = v;
}

// ---------------- weight transpose: (O,Cin,3,3) -> [k=t*Cin+c][m=o] ----------------
__global__ void wtrans_kernel(const float* __restrict__ w, float* __restrict__ wt, int O, int Cin) {
    int idx = blockIdx.x * blockDim.x + threadIdx.x;
    int total = O * Cin * 9;
    if (idx >= total) return;
    int t = idx % 9; int rest = idx / 9; int c = rest % Cin; int o = rest / Cin;
    wt[((size_t)(t * Cin + c)) * O + o] = w[idx];
}

// ---------------- 128x128 double-buffered SGEMM / implicit conv GEMM ----------------
// C[m,p] = bias[m] + sum_k A[k,m] * B[c(k)*strideC + (h+di)*Wp + (w+dj)]
// k = t*Cin + c (Cin = 1<<cinShift); p -> h = p>>wShift, w = p & wmask.
// 1-tap mode: cinShift >= log2(K) so t==0, Wp = N row width, wShift arbitrary.
__global__ __launch_bounds__(256, 2) void gemm128_kernel(
    const float* __restrict__ A, const float* __restrict__ B,
    const float* __restrict__ bias, float* __restrict__ C,
    int M, int N, int K, int cinShift, int Wp, int wShift, int strideC)
{
    __shared__ float As[2][16][128];
    __shared__ float Bs[2][16][128];
    int tid = threadIdx.x;
    int m0 = blockIdx.y * 128;
    int p0 = blockIdx.x * 128;
    int cmask = (1 << cinShift) - 1;
    int wmask = (1 << wShift) - 1;
    int tx = tid & 15, ty = tid >> 4;          // 16x16 threads, 8x8 microtile
    float acc[8][8] = {};
    float ra[8], rb[8];

    int lr = tid >> 7;                          // 0..1 (k-row pair base)
    int lc = tid & 127;                         // tile column
    int p = p0 + lc;
    int h = p >> wShift, w = p & wmask;
    bool aval = (m0 + lc) < M;

    int nk = K >> 4;
    // preload tile 0
#pragma unroll
    for (int r = 0; r < 8; r++) {
        int kk = lr + r * 2;
        As[0][kk][lc] = aval ? A[(size_t)kk * M + m0 + lc] : 0.f;
        int cch = kk & cmask, t = kk >> cinShift;
        int di = (t >= 6) ? 2 : (t >= 3 ? 1 : 0);
        int dj = t - di * 3;
        Bs[0][kk][lc] = B[(size_t)cch * strideC + (h + di) * Wp + (w + dj)];
    }
    __syncthreads();

    for (int kt = 0; kt < nk; kt++) {
        int cur = kt & 1;
        if (kt + 1 < nk) {
            int k0 = (kt + 1) << 4;
#pragma unroll
            for (int r = 0; r < 8; r++) {
                int k = k0 + lr + r * 2;
                ra[r] = aval ? A[(size_t)k * M + m0 + lc] : 0.f;
                int cch = k & cmask, t = k >> cinShift;
                int di = (t >= 6) ? 2 : (t >= 3 ? 1 : 0);
                int dj = t - di * 3;
                rb[r] = B[(size_t)cch * strideC + (h + di) * Wp + (w + dj)];
            }
        }
#pragma unroll
        for (int kk = 0; kk < 16; kk++) {
            float4 a0 = *(const float4*)&As[cur][kk][ty * 8];
            float4 a1 = *(const float4*)&As[cur][kk][ty * 8 + 4];
            float4 b0 = *(const float4*)&Bs[cur][kk][tx * 8];
            float4 b1 = *(const float4*)&Bs[cur][kk][tx * 8 + 4];
            float av[8] = {a0.x, a0.y, a0.z, a0.w, a1.x, a1.y, a1.z, a1.w};
            float bv[8] = {b0.x, b0.y, b0.z, b0.w, b1.x, b1.y, b1.z, b1.w};
#pragma unroll
            for (int i = 0; i < 8; i++)
#pragma unroll
                for (int j = 0; j < 8; j++)
                    acc[i][j] += av[i] * bv[j];
        }
        if (kt + 1 < nk) {
            int nxt = cur ^ 1;
#pragma unroll
            for (int r = 0; r < 8; r++) {
                As[nxt][lr + r * 2][lc] = ra[r];
                Bs[nxt][lr + r * 2][lc] = rb[r];
            }
            __syncthreads();
        }
    }

    // epilogue: vectorized stores
#pragma unroll
    for (int i = 0; i < 8; i++) {
        int m = m0 + ty * 8 + i;
        if (m < M) {
            float bv = bias ? bias[m] : 0.f;
            float* crow = C + (size_t)m * N + p0 + tx * 8;
            float4 v0 = make_float4(acc[i][0] + bv, acc[i][1] + bv, acc[i][2] + bv, acc[i][3] + bv);
            float4 v1 = make_float4(acc[i][4] + bv, acc[i][5] + bv, acc[i][6] + bv, acc[i][7] + bv);
            *(float4*)&crow[0] = v0;
            *(float4*)&crow[4] = v1;
        }
    }
}

// ---------------- guide kernel: kk[t,p] = exp(-0.5*sum_c (g_pad[nbr]-g[ctr])^2) ----------------
__global__ __launch_bounds__(256) void kk_kernel(const float* __restrict__ g,
                                                 float* __restrict__ kkout,
                                                 int C, int H, int W) {
    __shared__ float tile[4][18][18];
    int tx = threadIdx.x & 15, ty = threadIdx.x >> 4;
    int w0 = blockIdx.x * 16, h0 = blockIdx.y * 16;
    float acc[9] = {};
    int HW = H * W;
    for (int c0 = 0; c0 < C; c0 += 4) {
        __syncthreads();
        for (int idx = threadIdx.x; idx < 4 * 324; idx += 256) {
            int cc = idx / 324, rem = idx % 324;
            int yy = rem / 18, xx = rem % 18;
            int gy = h0 + yy - 1, gx = w0 + xx - 1;
            float v = 0.f;
            if (gy >= 0 && gy < H && gx >= 0 && gx < W)
                v = g[(size_t)(c0 + cc) * HW + gy * W + gx];
            tile[cc][yy][xx] = v;
        }
        __syncthreads();
#pragma unroll
        for (int cc = 0; cc < 4; cc++) {
            float ctr = tile[cc][ty + 1][tx + 1];
#pragma unroll
            for (int t = 0; t < 9; t++) {
                float d = tile[cc][ty + t / 3][tx + t % 3] - ctr;
                acc[t] += d * d;
            }
        }
    }
    int p = (h0 + ty) * W + (w0 + tx);
#pragma unroll
    for (int t = 0; t < 9; t++)
        kkout[(size_t)t * HW + p] = __expf(-0.5f * acc[t]);
}

// ---------------- PAC combine ----------------
__global__ void pac_combine_kernel(const float* __restrict__ z, const float* __restrict__ kkb,
                                   const float* __restrict__ bias, float* __restrict__ out,
                                   int Ho, int Wo, int Hin, int Win, int woShift) {
    int o = blockIdx.y;
    int p = blockIdx.x * blockDim.x + threadIdx.x;
    int np = Ho * Wo;
    if (p >= np) return;
    int h = p >> woShift, w = p & (Wo - 1);
    int nsrc = Hin * Win;
    float s = bias[o];
#pragma unroll
    for (int i = 0; i < 3; i++) {
        int hi = h + i;
        if (!(hi & 1)) continue;
        int sh = (hi - 1) >> 1;
        if (sh >= Hin) continue;
#pragma unroll
        for (int j = 0; j < 3; j++) {
            int wj = w + j;
            if (!(wj & 1)) continue;
            int sw = (wj - 1) >> 1;
            if (sw >= Win) continue;
            int t = i * 3 + j;
            s += kkb[(size_t)t * np + p] * z[(size_t)(o * 9 + t) * nsrc + sh * Win + sw];
        }
    }
    out[(size_t)o * np + p] = s;
}

// ---------------- final 3x3 conv, 64 -> 3 channels, 256x256 ----------------
__global__ __launch_bounds__(256) void conv_out_kernel(const float* __restrict__ in,
                                                       const float* __restrict__ wgt,
                                                       const float* __restrict__ bias,
                                                       float* __restrict__ out) {
    __shared__ float ws[3 * 64 * 9];
    __shared__ float tile[8][18][18];
    const int H = 256, W = 256;
    for (int idx = threadIdx.x; idx < 1728; idx += 256) ws[idx] = wgt[idx];
    int tx = threadIdx.x & 15, ty = threadIdx.x >> 4;
    int w0 = blockIdx.x * 16, h0 = blockIdx.y * 16;
    float acc[3] = {bias[0], bias[1], bias[2]};
    for (int c0 = 0; c0 < 64; c0 += 8) {
        __syncthreads();
        for (int idx = threadIdx.x; idx < 8 * 324; idx += 256) {
            int cc = idx / 324, rem = idx % 324;
            int yy = rem / 18, xx = rem % 18;
            int gy = h0 + yy - 1, gx = w0 + xx - 1;
            float v = 0.f;
            if (gy >= 0 && gy < H && gx >= 0 && gx < W)
                v = in[(size_t)(c0 + cc) * H * W + gy * W + gx];
            tile[cc][yy][xx] = v;
        }
        __syncthreads();
#pragma unroll
        for (int cc = 0; cc < 8; cc++) {
            float v[9];
#pragma unroll
            for (int t = 0; t < 9; t++)
                v[t] = tile[cc][ty + t / 3][tx + t % 3];
#pragma unroll
            for (int o = 0; o < 3; o++)
#pragma unroll
                for (int t = 0; t < 9; t++)
                    acc[o] += v[t] * ws[(o * 64 + c0 + cc) * 9 + t];
        }
    }
    int p = (h0 + ty) * W + (w0 + tx);
#pragma unroll
    for (int o = 0; o < 3; o++) out[(size_t)o * H * W + p] = acc[o];
}

// ---------------- host ----------------
extern "C" void kernel_launch(void* const* d_in, const int* in_sizes, int n_in,
                              void* d_out, int out_size) {
    const float* x       = (const float*)d_in[0];
    const float* ef2     = (const float*)d_in[1];
    const float* ef1     = (const float*)d_in[2];
    const float* w_adj2  = (const float*)d_in[3];
    const float* b_adj2  = (const float*)d_in[4];
    const float* w_adj1  = (const float*)d_in[5];
    const float* b_adj1  = (const float*)d_in[6];
    const float* w_pac16 = (const float*)d_in[7];
    const float* b_pac16 = (const float*)d_in[8];
    const float* w_pac20 = (const float*)d_in[9];
    const float* b_pac20 = (const float*)d_in[10];
    const float* w_out   = (const float*)d_in[11];
    const float* b_out   = (const float*)d_in[12];
    float* out = (float*)d_out;

    float* S = nullptr;
    cudaGetSymbolAddress((void**)&S, g_scratch);
    float* xbuf0 = S + OFF_XBUF0;
    float* pad2  = S + OFF_PAD2;
    float* wt2   = S + OFF_WT2;
    float* g2    = S + OFF_G2;
    float* kk1   = S + OFF_KK1;
    float* z1    = S + OFF_Z1;
    float* x1    = S + OFF_X1;
    float* pad1  = S + OFF_PAD1;
    float* wt1   = S + OFF_WT1;
    float* g1    = S + OFF_G1;
    float* kk2   = S + OFF_KK2;
    float* z2    = S + OFF_Z2;
    float* x2    = S + OFF_X2;

    // stage 0: double inorm on x (256 ch, 64x64)
    inorm2_kernel<<<256, 256>>>(x, xbuf0, 4096);

    // guide conv g2 = conv3x3(ef_lv2; 128->256 @128x128)
    pad_kernel<<<dim3(67, 128), 256>>>(ef2, pad2, 128, 128);
    wtrans_kernel<<<(294912 + 255) / 256, 256>>>(w_adj2, wt2, 256, 128);
    gemm128_kernel<<<dim3(16384 / 128, 2), 256>>>(wt2, pad2, b_adj2, g2,
                                                  256, 16384, 1152, 7, 130, 7, 16900);
    // PAC 16: kk from g2 (256 ch), z1 = W^T x, combine -> x1 (128 ch @128x128)
    kk_kernel<<<dim3(8, 8), 256>>>(g2, kk1, 256, 128, 128);
    gemm128_kernel<<<dim3(4096 / 128, 9), 256>>>(w_pac16, xbuf0, nullptr, z1,
                                                 1152, 4096, 256, 8, 4096, 12, 4096);
    pac_combine_kernel<<<dim3(64, 128), 256>>>(z1, kk1, b_pac16, x1, 128, 128, 64, 64, 7);
    inorm2_kernel<<<128, 256>>>(x1, x1, 16384);

    // guide conv g1 = conv3x3(ef_lv1; 64->128 @256x256)
    pad_kernel<<<dim3(261, 64), 256>>>(ef1, pad1, 256, 256);
    wtrans_kernel<<<(73728 + 255) / 256, 256>>>(w_adj1, wt1, 128, 64);
    gemm128_kernel<<<dim3(65536 / 128, 1), 256>>>(wt1, pad1, b_adj1, g1,
                                                  128, 65536, 576, 6, 258, 8, 66564);
    // PAC 20: kk from g1 (128 ch), z2, combine -> x2 (64 ch @256x256)
    kk_kernel<<<dim3(16, 16), 256>>>(g1, kk2, 128, 256, 256);
    gemm128_kernel<<<dim3(16384 / 128, 5), 256>>>(w_pac20, x1, nullptr, z2,
                                                  576, 16384, 128, 7, 16384, 14, 16384);
    pac_combine_kernel<<<dim3(256, 64), 256>>>(z2, kk2, b_pac20, x2, 256, 256, 128, 128, 8);
    inorm2_kernel<<<64, 256>>>(x2, x2, 65536);

    // final conv 64 -> 3
    conv_out_kernel<<<dim3(16, 16), 256>>>(x2, w_out, b_out, out);
}

// round 7
// speedup vs baseline: 1.3435x; 1.3319x over previous
#include <cuda_runtime.h>
#include <cuda_bf16.h>
#include <cstdint>

#define EPS 1e-5f

// ---------------- scratch layout (floats) ----------------
static const size_t OFF_XBUF0 = 0;          // 256*4096
static const size_t OFF_PAD2  = 1048576;    // 128*130*130
static const size_t OFF_WT2   = 3211776;    // 1152*256
static const size_t OFF_G2    = 3506688;    // 256*16384
static const size_t OFF_KK1   = 7700992;    // 9*16384
static const size_t OFF_Z1    = 7848448;    // 1152*4096
static const size_t OFF_X1    = 12567040;   // 128*16384
static const size_t OFF_PAD1  = 14664192;   // 64*258*258
static const size_t OFF_WT1   = 18924288;   // 576*128
static const size_t OFF_G1    = 18998016;   // 128*65536
static const size_t OFF_KK2   = 27386624;   // 9*65536
static const size_t OFF_Z2    = 27976448;   // 576*16384
static const size_t OFF_X2    = 37413632;   // 64*65536
static const size_t OFF_KP1   = 41607936;   // 8*9*16384
static const size_t OFF_KP2   = 42787584;   // 4*9*65536
static const size_t SCRATCH_FLOATS = 45146880; // ~181 MB

__device__ float g_scratch[SCRATCH_FLOATS];

__device__ __forceinline__ uint32_t pack_bf(float a, float b) {
    __nv_bfloat162 t = __floats2bfloat162_rn(a, b);
    return *reinterpret_cast<uint32_t*>(&t);
}

__device__ __forceinline__ void mma16816(float* d, const uint32_t* a, uint32_t b0, uint32_t b1) {
    asm volatile(
        "mma.sync.aligned.m16n8k16.row.col.f32.bf16.bf16.f32 "
        "{%0,%1,%2,%3}, {%4,%5,%6,%7}, {%8,%9}, {%0,%1,%2,%3};"
        : "+f"(d[0]), "+f"(d[1]), "+f"(d[2]), "+f"(d[3])
        : "r"(a[0]), "r"(a[1]), "r"(a[2]), "r"(a[3]), "r"(b0), "r"(b1));
}

// ================= HMMA bf16x3-split GEMM =================
// C[m,p] = bias[m] + sum_k A[k][m] * Bgather(k,p)
// Per 32-fp32 K-chunk: 96 bf16 cols: A=[hi|hi|lo], B=[hi|lo|hi]
// smem tiles: [128 rows][104 bf16] padded (rows: A=m, B=p)
#define SMS 104
__global__ __launch_bounds__(256, 2) void gemm_mma_kernel(
    const float* __restrict__ A, const float* __restrict__ B,
    const float* __restrict__ bias, float* __restrict__ C,
    int M, int N, int K, int cinShift, int Wp, int wShift, int strideC)
{
    extern __shared__ __nv_bfloat16 smem_bf[];
    __nv_bfloat16* sA = smem_bf;
    __nv_bfloat16* sB = smem_bf + 128 * SMS;

    int tid = threadIdx.x;
    int m0 = blockIdx.y * 128;
    int p0 = blockIdx.x * 128;
    int cmask = (1 << cinShift) - 1;
    int wmask = (1 << wShift) - 1;

    int lane = tid & 31, wrp = tid >> 5;
    int wm = wrp & 3, wn = wrp >> 2;       // warp tile: rows wm*32(+32), cols wn*64(+64)
    int r = lane >> 2, cp = (lane & 3) * 2;

    float acc[2][8][4] = {};

    int nc = K >> 5;
    for (int c = 0; c < nc; c++) {
        int k0 = c << 5;
        __syncthreads();   // guard smem reuse
#pragma unroll 4
        for (int it = 0; it < 16; it++) {
            int idx = it * 256 + tid;
            int row = idx & 127;
            int kp = (idx >> 7) & 15;
            int k = k0 + kp * 2;
            float v0, v1;
            if (idx < 2048) {
                int m = m0 + row;
                bool val = m < M;
                v0 = val ? A[(size_t)k * M + m] : 0.f;
                v1 = val ? A[(size_t)(k + 1) * M + m] : 0.f;
            } else {
                int p = p0 + row;
                int h = p >> wShift, w = p & wmask;
                {
                    int cch = k & cmask, t = k >> cinShift;
                    int di = (t >= 6) ? 2 : (t >= 3 ? 1 : 0);
                    int dj = t - di * 3;
                    v0 = B[(size_t)cch * strideC + (h + di) * Wp + (w + dj)];
                }
                {
                    int k1 = k + 1;
                    int cch = k1 & cmask, t = k1 >> cinShift;
                    int di = (t >= 6) ? 2 : (t >= 3 ? 1 : 0);
                    int dj = t - di * 3;
                    v1 = B[(size_t)cch * strideC + (h + di) * Wp + (w + dj)];
                }
            }
            float h0 = __bfloat162float(__float2bfloat16(v0));
            float h1 = __bfloat162float(__float2bfloat16(v1));
            uint32_t hp = pack_bf(v0, v1);
            uint32_t lp = pack_bf(v0 - h0, v1 - h1);
            int col = kp * 2;
            __nv_bfloat16* base = (idx < 2048) ? sA : sB;
            uint32_t* p0w = (uint32_t*)(base + row * SMS + col);
            p0w[0]  = hp;                               // cols [0..31]
            p0w[16] = (idx < 2048) ? hp : lp;           // cols [32..63]
            p0w[32] = (idx < 2048) ? lp : hp;           // cols [64..95]
        }
        __syncthreads();

#pragma unroll
        for (int ks = 0; ks < 6; ks++) {
            int kb = ks * 16;
            uint32_t af[2][4];
#pragma unroll
            for (int mt = 0; mt < 2; mt++) {
                const __nv_bfloat16* pa = sA + (wm * 32 + mt * 16 + r) * SMS + kb + cp;
                af[mt][0] = *(const uint32_t*)pa;
                af[mt][1] = *(const uint32_t*)(pa + 8 * SMS);
                af[mt][2] = *(const uint32_t*)(pa + 8);
                af[mt][3] = *(const uint32_t*)(pa + 8 * SMS + 8);
            }
#pragma unroll
            for (int nt = 0; nt < 8; nt++) {
                const __nv_bfloat16* pb = sB + (wn * 64 + nt * 8 + r) * SMS + kb + cp;
                uint32_t b0 = *(const uint32_t*)pb;
                uint32_t b1 = *(const uint32_t*)(pb + 8);
                mma16816(acc[0][nt], af[0], b0, b1);
                mma16816(acc[1][nt], af[1], b0, b1);
            }
        }
    }

    // epilogue: registers -> C
#pragma unroll
    for (int mt = 0; mt < 2; mt++) {
        int mA = m0 + wm * 32 + mt * 16 + r;
        int mB = mA + 8;
        float bvA = (bias && mA < M) ? bias[mA] : 0.f;
        float bvB = (bias && mB < M) ? bias[mB] : 0.f;
#pragma unroll
        for (int nt = 0; nt < 8; nt++) {
            int n = p0 + wn * 64 + nt * 8 + cp;
            if (mA < M) {
                float2 v = make_float2(acc[mt][nt][0] + bvA, acc[mt][nt][1] + bvA);
                *(float2*)(C + (size_t)mA * N + n) = v;
            }
            if (mB < M) {
                float2 v = make_float2(acc[mt][nt][2] + bvB, acc[mt][nt][3] + bvB);
                *(float2*)(C + (size_t)mB * N + n) = v;
            }
        }
    }
}
static const int SMEM_MMA = 2 * 128 * SMS * 2;  // 53248 B

// ---------------- fused double instance-norm + residual (x2), float4 ----------------
__global__ __launch_bounds__(256) void inorm2_kernel(const float* __restrict__ in,
                                                     float* __restrict__ out, int HW) {
    int c = blockIdx.x;
    const float4* x4 = (const float4*)(in + (size_t)c * HW);
    float4* y4 = (float4*)(out + (size_t)c * HW);
    int n4 = HW >> 2;
    float s = 0.f, s2 = 0.f;
    for (int i = threadIdx.x; i < n4; i += 256) {
        float4 v = x4[i];
        s += v.x + v.y + v.z + v.w;
        s2 += v.x * v.x + v.y * v.y + v.z * v.z + v.w * v.w;
    }
    __shared__ float rs[256], rq[256];
    rs[threadIdx.x] = s; rq[threadIdx.x] = s2;
    __syncthreads();
    for (int o = 128; o > 0; o >>= 1) {
        if (threadIdx.x < o) { rs[threadIdx.x] += rs[threadIdx.x + o]; rq[threadIdx.x] += rq[threadIdx.x + o]; }
        __syncthreads();
    }
    float m = rs[0] / (float)HW;
    float v = rq[0] / (float)HW - m * m;
    if (v < 0.f) v = 0.f;
    float a = 1.f + rsqrtf(v + EPS);
    float scale = a * (1.f + rsqrtf(v * a * a + EPS));
    for (int i = threadIdx.x; i < n4; i += 256) {
        float4 t = x4[i];
        t.x = m + (t.x - m) * scale;
        t.y = m + (t.y - m) * scale;
        t.z = m + (t.z - m) * scale;
        t.w = m + (t.w - m) * scale;
        y4[i] = t;
    }
}

// ---------------- zero-pad (H,W) -> (H+2,W+2) ----------------
__global__ void pad_kernel(const float* __restrict__ in, float* __restrict__ out, int H, int W) {
    int c = blockIdx.y;
    int Hp = H + 2, Wp = W + 2;
    int idx = blockIdx.x * blockDim.x + threadIdx.x;
    if (idx >= Hp * Wp) return;
    int y = idx / Wp, x = idx % Wp;
    float v = 0.f;
    if (y >= 1 && y <= H && x >= 1 && x <= W)
        v = in[((size_t)c * H + (y - 1)) * W + (x - 1)];
    out[(size_t)c * Hp * Wp + idx] = v;
}

// ---------------- weight transpose: (O,Cin,3,3) -> [k=t*Cin+c][m=o] ----------------
__global__ void wtrans_kernel(const float* __restrict__ w, float* __restrict__ wt, int O, int Cin) {
    int idx = blockIdx.x * blockDim.x + threadIdx.x;
    int total = O * Cin * 9;
    if (idx >= total) return;
    int t = idx % 9; int rest = idx / 9; int c = rest % Cin; int o = rest / Cin;
    wt[((size_t)(t * Cin + c)) * O + o] = w[idx];
}

// ---------------- kk partial: per (tile, 32-ch chunk) sum of squared diffs ----------------
__global__ __launch_bounds__(256) void kk_partial_kernel(const float* __restrict__ g,
                                                         float* __restrict__ part,
                                                         int H, int W) {
    __shared__ float tile[4][18][18];
    int tx = threadIdx.x & 15, ty = threadIdx.x >> 4;
    int w0 = blockIdx.x * 16, h0 = blockIdx.y * 16;
    int HW = H * W;
    float acc[9] = {};
    int cbase = blockIdx.z * 32;
    for (int c0 = cbase; c0 < cbase + 32; c0 += 4) {
        __syncthreads();
        for (int idx = threadIdx.x; idx < 4 * 324; idx += 256) {
            int cc = idx / 324, rem = idx % 324;
            int yy = rem / 18, xx = rem % 18;
            int gy = h0 + yy - 1, gx = w0 + xx - 1;
            float v = 0.f;
            if (gy >= 0 && gy < H && gx >= 0 && gx < W)
                v = g[(size_t)(c0 + cc) * HW + gy * W + gx];
            tile[cc][yy][xx] = v;
        }
        __syncthreads();
#pragma unroll
        for (int cc = 0; cc < 4; cc++) {
            float ctr = tile[cc][ty + 1][tx + 1];
#pragma unroll
            for (int t = 0; t < 9; t++) {
                float d = tile[cc][ty + t / 3][tx + t % 3] - ctr;
                acc[t] += d * d;
            }
        }
    }
    int p = (h0 + ty) * W + (w0 + tx);
#pragma unroll
    for (int t = 0; t < 9; t++)
        part[((size_t)(blockIdx.z * 9 + t)) * HW + p] = acc[t];
}

__global__ void kk_final_kernel(const float* __restrict__ part, float* __restrict__ kkout,
                                int HW, int nchunk) {
    int i = blockIdx.x * 256 + threadIdx.x;
    if (i >= 9 * HW) return;
    int t = i / HW, p = i - t * HW;
    float s = 0.f;
    for (int c = 0; c < nchunk; c++)
        s += part[((size_t)(c * 9 + t)) * HW + p];
    kkout[(size_t)t * HW + p] = __expf(-0.5f * s);
}

// ---------------- PAC combine ----------------
__global__ void pac_combine_kernel(const float* __restrict__ z, const float* __restrict__ kkb,
                                   const float* __restrict__ bias, float* __restrict__ out,
                                   int Ho, int Wo, int Hin, int Win, int woShift) {
    int o = blockIdx.y;
    int p = blockIdx.x * blockDim.x + threadIdx.x;
    int np = Ho * Wo;
    if (p >= np) return;
    int h = p >> woShift, w = p & (Wo - 1);
    int nsrc = Hin * Win;
    float s = bias[o];
#pragma unroll
    for (int i = 0; i < 3; i++) {
        int hi = h + i;
        if (!(hi & 1)) continue;
        int sh = (hi - 1) >> 1;
        if (sh >= Hin) continue;
#pragma unroll
        for (int j = 0; j < 3; j++) {
            int wj = w + j;
            if (!(wj & 1)) continue;
            int sw = (wj - 1) >> 1;
            if (sw >= Win) continue;
            int t = i * 3 + j;
            s += kkb[(size_t)t * np + p] * z[(size_t)(o * 9 + t) * nsrc + sh * Win + sw];
        }
    }
    out[(size_t)o * np + p] = s;
}

// ---------------- final 3x3 conv, 64 -> 3 channels, 256x256 ----------------
__global__ __launch_bounds__(256) void conv_out_kernel(const float* __restrict__ in,
                                                       const float* __restrict__ wgt,
                                                       const float* __restrict__ bias,
                                                       float* __restrict__ out) {
    __shared__ float ws[3 * 64 * 9];
    __shared__ float tile[8][18][18];
    const int H = 256, W = 256;
    for (int idx = threadIdx.x; idx < 1728; idx += 256) ws[idx] = wgt[idx];
    int tx = threadIdx.x & 15, ty = threadIdx.x >> 4;
    int w0 = blockIdx.x * 16, h0 = blockIdx.y * 16;
    float acc[3] = {bias[0], bias[1], bias[2]};
    for (int c0 = 0; c0 < 64; c0 += 8) {
        __syncthreads();
        for (int idx = threadIdx.x; idx < 8 * 324; idx += 256) {
            int cc = idx / 324, rem = idx % 324;
            int yy = rem / 18, xx = rem % 18;
            int gy = h0 + yy - 1, gx = w0 + xx - 1;
            float v = 0.f;
            if (gy >= 0 && gy < H && gx >= 0 && gx < W)
                v = in[(size_t)(c0 + cc) * H * W + gy * W + gx];
            tile[cc][yy][xx] = v;
        }
        __syncthreads();
#pragma unroll
        for (int cc = 0; cc < 8; cc++) {
            float v[9];
#pragma unroll
            for (int t = 0; t < 9; t++)
                v[t] = tile[cc][ty + t / 3][tx + t % 3];
#pragma unroll
            for (int o = 0; o < 3; o++)
#pragma unroll
                for (int t = 0; t < 9; t++)
                    acc[o] += v[t] * ws[(o * 64 + c0 + cc) * 9 + t];
        }
    }
    int p = (h0 + ty) * W + (w0 + tx);
#pragma unroll
    for (int o = 0; o < 3; o++) out[(size_t)o * H * W + p] = acc[o];
}

// ---------------- host ----------------
extern "C" void kernel_launch(void* const* d_in, const int* in_sizes, int n_in,
                              void* d_out, int out_size) {
    const float* x       = (const float*)d_in[0];
    const float* ef2     = (const float*)d_in[1];
    const float* ef1     = (const float*)d_in[2];
    const float* w_adj2  = (const float*)d_in[3];
    const float* b_adj2  = (const float*)d_in[4];
    const float* w_adj1  = (const float*)d_in[5];
    const float* b_adj1  = (const float*)d_in[6];
    const float* w_pac16 = (const float*)d_in[7];
    const float* b_pac16 = (const float*)d_in[8];
    const float* w_pac20 = (const float*)d_in[9];
    const float* b_pac20 = (const float*)d_in[10];
    const float* w_out   = (const float*)d_in[11];
    const float* b_out   = (const float*)d_in[12];
    float* out = (float*)d_out;

    float* S = nullptr;
    cudaGetSymbolAddress((void**)&S, g_scratch);
    float* xbuf0 = S + OFF_XBUF0;
    float* pad2  = S + OFF_PAD2;
    float* wt2   = S + OFF_WT2;
    float* g2    = S + OFF_G2;
    float* kk1   = S + OFF_KK1;
    float* z1    = S + OFF_Z1;
    float* x1    = S + OFF_X1;
    float* pad1  = S + OFF_PAD1;
    float* wt1   = S + OFF_WT1;
    float* g1    = S + OFF_G1;
    float* kk2   = S + OFF_KK2;
    float* z2    = S + OFF_Z2;
    float* x2    = S + OFF_X2;
    float* kp1   = S + OFF_KP1;
    float* kp2   = S + OFF_KP2;

    cudaFuncSetAttribute(gemm_mma_kernel, cudaFuncAttributeMaxDynamicSharedMemorySize, SMEM_MMA);

    // stage 0: double inorm on x (256 ch, 64x64)
    inorm2_kernel<<<256, 256>>>(x, xbuf0, 4096);

    // guide conv g2 = conv3x3(ef_lv2; 128->256 @128x128)
    pad_kernel<<<dim3(67, 128), 256>>>(ef2, pad2, 128, 128);
    wtrans_kernel<<<(294912 + 255) / 256, 256>>>(w_adj2, wt2, 256, 128);
    gemm_mma_kernel<<<dim3(128, 2), 256, SMEM_MMA>>>(wt2, pad2, b_adj2, g2,
                                                     256, 16384, 1152, 7, 130, 7, 16900);
    // PAC 16
    kk_partial_kernel<<<dim3(8, 8, 8), 256>>>(g2, kp1, 128, 128);
    kk_final_kernel<<<(9 * 16384 + 255) / 256, 256>>>(kp1, kk1, 16384, 8);
    gemm_mma_kernel<<<dim3(32, 9), 256, SMEM_MMA>>>(w_pac16, xbuf0, nullptr, z1,
                                                    1152, 4096, 256, 8, 4096, 12, 4096);
    pac_combine_kernel<<<dim3(64, 128), 256>>>(z1, kk1, b_pac16, x1, 128, 128, 64, 64, 7);
    inorm2_kernel<<<128, 256>>>(x1, x1, 16384);

    // guide conv g1 = conv3x3(ef_lv1; 64->128 @256x256)
    pad_kernel<<<dim3(261, 64), 256>>>(ef1, pad1, 256, 256);
    wtrans_kernel<<<(73728 + 255) / 256, 256>>>(w_adj1, wt1, 128, 64);
    gemm_mma_kernel<<<dim3(512, 1), 256, SMEM_MMA>>>(wt1, pad1, b_adj1, g1,
                                                     128, 65536, 576, 6, 258, 8, 66564);
    // PAC 20
    kk_partial_kernel<<<dim3(16, 16, 4), 256>>>(g1, kp2, 256, 256);
    kk_final_kernel<<<(9 * 65536 + 255) / 256, 256>>>(kp2, kk2, 65536, 4);
    gemm_mma_kernel<<<dim3(128, 5), 256, SMEM_MMA>>>(w_pac20, x1, nullptr, z2,
                                                     576, 16384, 128, 7, 16384, 14, 16384);
    pac_combine_kernel<<<dim3(256, 64), 256>>>(z2, kk2, b_pac20, x2, 256, 256, 128, 128, 8);
    inorm2_kernel<<<64, 256>>>(x2, x2, 65536);

    // final conv 64 -> 3
    conv_out_kernel<<<dim3(16, 16), 256>>>(x2, w_out, b_out, out);
}

// round 8
// speedup vs baseline: 1.6241x; 1.2088x over previous
#include <cuda_runtime.h>
#include <cuda_bf16.h>
#include <cstdint>

#define EPS 1e-5f

// ---------------- scratch layout (floats) ----------------
static const size_t OFF_XBUF0 = 0;           // 1,048,576
static const size_t OFF_G2    = 1048576;     // 4,194,304
static const size_t OFF_KK1   = 5242880;     // 147,456
static const size_t OFF_Z1    = 5390336;     // 4,718,592
static const size_t OFF_X1    = 10108928;    // 2,097,152
static const size_t OFF_G1    = 12206080;    // 8,388,608
static const size_t OFF_KK2   = 20594688;    // 589,824
static const size_t OFF_Z2    = 21184512;    // 9,437,184
static const size_t OFF_X2    = 30621696;    // 4,194,304
static const size_t OFF_KP1   = 34816000;    // 1,179,648
static const size_t OFF_KP2   = 35995648;    // 2,359,296
// bf16 regions (size in floats = elems/2)
static const size_t OFF_XSH   = 38354944;    // 524,288
static const size_t OFF_XSL   = 38879232;    // 524,288
static const size_t OFF_P2H   = 39403520;    // 1,081,600
static const size_t OFF_P2L   = 40485120;    // 1,081,600
static const size_t OFF_P1H   = 41566720;    // 2,130,048
static const size_t OFF_P1L   = 43696768;    // 2,130,048
static const size_t OFF_X1H   = 45826816;    // 1,048,576
static const size_t OFF_X1L   = 46875392;    // 1,048,576
static const size_t OFF_AW2   = 47923968;    // 442,368
static const size_t OFF_AWP16 = 48366336;    // 442,368
static const size_t OFF_AW1   = 48808704;    // 110,592
static const size_t OFF_AWP20 = 48919296;    // 122,880 (640 rows, padded, zero-backed)
static const size_t SCRATCH_FLOATS = 49042176; // ~196 MB

__device__ float g_scratch[SCRATCH_FLOATS];

// ================= helpers =================
__device__ __forceinline__ uint32_t smem_u32(const void* p) {
    uint32_t a;
    asm("{ .reg .u64 t; cvta.to.shared.u64 t, %1; cvt.u32.u64 %0, t; }" : "=r"(a) : "l"(p));
    return a;
}
__device__ __forceinline__ void cpasync16(uint32_t dst, const void* src) {
    asm volatile("cp.async.cg.shared.global [%0], [%1], 16;" :: "r"(dst), "l"(src));
}
__device__ __forceinline__ void cpcommit() {
    asm volatile("cp.async.commit_group;" ::: "memory");
}
__device__ __forceinline__ void mma16816(float* d, const uint32_t* a, uint32_t b0, uint32_t b1) {
    asm volatile(
        "mma.sync.aligned.m16n8k16.row.col.f32.bf16.bf16.f32 "
        "{%0,%1,%2,%3}, {%4,%5,%6,%7}, {%8,%9}, {%0,%1,%2,%3};"
        : "+f"(d[0]), "+f"(d[1]), "+f"(d[2]), "+f"(d[3])
        : "r"(a[0]), "r"(a[1]), "r"(a[2]), "r"(a[3]), "r"(b0), "r"(b1));
}

// ================= async-pipelined HMMA GEMM =================
// C[m,p] = bias[m] + sum_{k'=0..3K-1} Asp[m][k'] * Bplane(term)[(h+di)*Wp+(w+dj)][c]
// Asp: [mRows][3K] bf16, terms [hi|hi|lo].  B planes: NHWC bf16 hi/lo.
// chunk = 32 bf16 k; 4-stage cp.async pipeline; tile 128x128, 8 warps.
#define NSTAGE 4
#define STG_B 20480              // per stage: A 128*80B + B 128*80B
#define SMSB 40                  // smem row stride in bf16
__global__ __launch_bounds__(256, 2) void gemm_as_kernel(
    const __nv_bfloat16* __restrict__ Ag, const __nv_bfloat16* __restrict__ Bhi,
    const __nv_bfloat16* __restrict__ Blo, const float* __restrict__ bias,
    float* __restrict__ C, int M, int N, int K, int cinShift, int Wp, int wShift)
{
    extern __shared__ char smem[];
    uint32_t sbase = smem_u32(smem);
    int tid = threadIdx.x, lane = tid & 31, wrp = tid >> 5;
    int wm = wrp & 3, wn = wrp >> 2, r = lane >> 2, cp2 = (lane & 3) * 2;
    int m0 = blockIdx.y * 128, p0 = blockIdx.x * 128;
    int K3 = K * 3, nk = K >> 5, ncc = nk * 3;
    int Cin = 1 << cinShift;

    // fill-thread coords: row (0..127), seg (0..1) -> 32B halves of 64B row
    int frow = tid & 127, fseg = tid >> 7;
    const char* arow = (const char*)(Ag + (size_t)(m0 + frow) * K3) + fseg * 32;
    int p = p0 + frow;
    int h = p >> wShift, w = p & ((1 << wShift) - 1);
    size_t bOff = (size_t)(h * Wp + w) * Cin + fseg * 16;   // elems
    uint32_t dA = sbase + frow * 80 + fseg * 32;
    uint32_t dB = dA + 10240;

    float acc[2][8][4] = {};

    // issue one chunk's cp.asyncs + commit
    auto issue = [&](int cc) {
        int stg = cc & 3;
        int term = (cc >= 2 * nk) ? 2 : (cc >= nk ? 1 : 0);
        int kk = (cc - term * nk) << 5;
        const char* As = arow + (size_t)(term * K + kk) * 2;
        uint32_t da = dA + stg * STG_B;
        cpasync16(da, As);
        cpasync16(da + 16, As + 16);
        int tap = kk >> cinShift;
        int c0 = kk & (Cin - 1);
        int di = (tap >= 6) ? 2 : (tap >= 3 ? 1 : 0);
        int dj = tap - di * 3;
        const __nv_bfloat16* plane = (term == 1) ? Blo : Bhi;
        const char* Bs = (const char*)(plane + bOff + (size_t)(di * Wp + dj) * Cin + c0);
        uint32_t db = dB + stg * STG_B;
        cpasync16(db, Bs);
        cpasync16(db + 16, Bs + 16);
        cpcommit();
    };

#pragma unroll
    for (int s = 0; s < NSTAGE - 1; s++) {
        if (s < ncc) issue(s); else cpcommit();
    }

    for (int cc = 0; cc < ncc; cc++) {
        asm volatile("cp.async.wait_group 2;" ::: "memory");
        __syncthreads();
        int stg = cc & 3;
        const __nv_bfloat16* tA = (const __nv_bfloat16*)(smem + stg * STG_B);
        const __nv_bfloat16* tB = tA + 5120;
#pragma unroll
        for (int ks = 0; ks < 2; ks++) {
            int kb = ks * 16;
            uint32_t af[2][4];
#pragma unroll
            for (int mt = 0; mt < 2; mt++) {
                const __nv_bfloat16* pa = tA + (wm * 32 + mt * 16 + r) * SMSB + kb + cp2;
                af[mt][0] = *(const uint32_t*)pa;
                af[mt][1] = *(const uint32_t*)(pa + 8 * SMSB);
                af[mt][2] = *(const uint32_t*)(pa + 8);
                af[mt][3] = *(const uint32_t*)(pa + 8 * SMSB + 8);
            }
#pragma unroll
            for (int nt = 0; nt < 8; nt++) {
                const __nv_bfloat16* pb = tB + (wn * 64 + nt * 8 + r) * SMSB + kb + cp2;
                uint32_t b0 = *(const uint32_t*)pb;
                uint32_t b1 = *(const uint32_t*)(pb + 8);
                mma16816(acc[0][nt], af[0], b0, b1);
                mma16816(acc[1][nt], af[1], b0, b1);
            }
        }
        int nx = cc + NSTAGE - 1;
        if (nx < ncc) issue(nx); else cpcommit();
    }

    // epilogue: registers -> C
#pragma unroll
    for (int mt = 0; mt < 2; mt++) {
        int mA = m0 + wm * 32 + mt * 16 + r;
        int mB = mA + 8;
        float bvA = (bias && mA < M) ? bias[mA] : 0.f;
        float bvB = (bias && mB < M) ? bias[mB] : 0.f;
#pragma unroll
        for (int nt = 0; nt < 8; nt++) {
            int n = p0 + wn * 64 + nt * 8 + cp2;
            if (mA < M)
                *(float2*)(C + (size_t)mA * N + n) =
                    make_float2(acc[mt][nt][0] + bvA, acc[mt][nt][1] + bvA);
            if (mB < M)
                *(float2*)(C + (size_t)mB * N + n) =
                    make_float2(acc[mt][nt][2] + bvB, acc[mt][nt][3] + bvB);
        }
    }
}
static const int SMEM_AS = NSTAGE * STG_B;  // 81920

// ---------------- NCHW float -> NHWC(padded) bf16 hi/lo, smem transpose ----------------
__global__ __launch_bounds__(256) void split_kernel(const float* __restrict__ in,
                                                    __nv_bfloat16* __restrict__ outH,
                                                    __nv_bfloat16* __restrict__ outL,
                                                    int C, int H, int W, int pad) {
    int Wp = W + 2 * pad, Hp = H + 2 * pad, Np = Hp * Wp;
    __shared__ float t[32][33];
    int p0 = blockIdx.x * 32, c0 = blockIdx.y * 32;
    int tx = threadIdx.x & 31, ty = threadIdx.x >> 5;   // 32 x 8
#pragma unroll
    for (int i = 0; i < 4; i++) {
        int c = c0 + ty + i * 8;
        int pos = p0 + tx;
        float v = 0.f;
        if (pos < Np) {
            int py = pos / Wp, px = pos - py * Wp;
            int iy = py - pad, ix = px - pad;
            if (iy >= 0 && iy < H && ix >= 0 && ix < W)
                v = in[((size_t)c * H + iy) * W + ix];
        }
        t[ty + i * 8][tx] = v;
    }
    __syncthreads();
#pragma unroll
    for (int i = 0; i < 4; i++) {
        int pos = p0 + ty + i * 8;
        int c = c0 + tx;
        if (pos < Np) {
            float v = t[tx][ty + i * 8];
            __nv_bfloat16 hb = __float2bfloat16(v);
            outH[(size_t)pos * C + c] = hb;
            outL[(size_t)pos * C + c] = __float2bfloat16(v - __bfloat162float(hb));
        }
    }
}

// ---------------- weight split: conv (O,Cin,3,3) -> Asp[m=o][3K], k = tap*Cin+c ----------------
__global__ void wsplit_conv_kernel(const float* __restrict__ w, __nv_bfloat16* __restrict__ out,
                                   int O, int Cin, int cinShift) {
    int K = 9 * Cin, K3 = 3 * K;
    int idx = blockIdx.x * 256 + threadIdx.x;
    if (idx >= O * K) return;
    int m = idx / K, k = idx - m * K;
    int c = k & (Cin - 1), t = k >> cinShift;
    float v = w[((size_t)m * Cin + c) * 9 + t];
    __nv_bfloat16 hb = __float2bfloat16(v);
    __nv_bfloat16 lb = __float2bfloat16(v - __bfloat162float(hb));
    out[(size_t)m * K3 + k] = hb;
    out[(size_t)m * K3 + K + k] = hb;
    out[(size_t)m * K3 + 2 * K + k] = lb;
}

// ---------------- weight split: pac (Cin,OC,3,3) -> Asp[m=o*9+t][3K], k = c ----------------
__global__ void wsplit_pac_kernel(const float* __restrict__ w, __nv_bfloat16* __restrict__ out,
                                  int OC, int Cin) {
    int M = OC * 9, K = Cin, K3 = 3 * K;
    int idx = blockIdx.x * 256 + threadIdx.x;
    if (idx >= M * K) return;
    int m = idx / K, k = idx - m * K;
    int o = m / 9, t = m - o * 9;
    float v = w[((size_t)k * OC + o) * 9 + t];
    __nv_bfloat16 hb = __float2bfloat16(v);
    __nv_bfloat16 lb = __float2bfloat16(v - __bfloat162float(hb));
    out[(size_t)m * K3 + k] = hb;
    out[(size_t)m * K3 + K + k] = hb;
    out[(size_t)m * K3 + 2 * K + k] = lb;
}

// ---------------- fused double instance-norm + residual (x2), float4 ----------------
__global__ __launch_bounds__(256) void inorm2_kernel(const float* __restrict__ in,
                                                     float* __restrict__ out, int HW) {
    int c = blockIdx.x;
    const float4* x4 = (const float4*)(in + (size_t)c * HW);
    float4* y4 = (float4*)(out + (size_t)c * HW);
    int n4 = HW >> 2;
    float s = 0.f, s2 = 0.f;
    for (int i = threadIdx.x; i < n4; i += 256) {
        float4 v = x4[i];
        s += v.x + v.y + v.z + v.w;
        s2 += v.x * v.x + v.y * v.y + v.z * v.z + v.w * v.w;
    }
    __shared__ float rs[256], rq[256];
    rs[threadIdx.x] = s; rq[threadIdx.x] = s2;
    __syncthreads();
    for (int o = 128; o > 0; o >>= 1) {
        if (threadIdx.x < o) { rs[threadIdx.x] += rs[threadIdx.x + o]; rq[threadIdx.x] += rq[threadIdx.x + o]; }
        __syncthreads();
    }
    float m = rs[0] / (float)HW;
    float v = rq[0] / (float)HW - m * m;
    if (v < 0.f) v = 0.f;
    float a = 1.f + rsqrtf(v + EPS);
    float scale = a * (1.f + rsqrtf(v * a * a + EPS));
    for (int i = threadIdx.x; i < n4; i += 256) {
        float4 t = x4[i];
        t.x = m + (t.x - m) * scale;
        t.y = m + (t.y - m) * scale;
        t.z = m + (t.z - m) * scale;
        t.w = m + (t.w - m) * scale;
        y4[i] = t;
    }
}

// ---------------- kk partial ----------------
__global__ __launch_bounds__(256) void kk_partial_kernel(const float* __restrict__ g,
                                                         float* __restrict__ part,
                                                         int H, int W) {
    __shared__ float tile[4][18][18];
    int tx = threadIdx.x & 15, ty = threadIdx.x >> 4;
    int w0 = blockIdx.x * 16, h0 = blockIdx.y * 16;
    int HW = H * W;
    float acc[9] = {};
    int cbase = blockIdx.z * 32;
    for (int c0 = cbase; c0 < cbase + 32; c0 += 4) {
        __syncthreads();
        for (int idx = threadIdx.x; idx < 4 * 324; idx += 256) {
            int cc = idx / 324, rem = idx % 324;
            int yy = rem / 18, xx = rem % 18;
            int gy = h0 + yy - 1, gx = w0 + xx - 1;
            float v = 0.f;
            if (gy >= 0 && gy < H && gx >= 0 && gx < W)
                v = g[(size_t)(c0 + cc) * HW + gy * W + gx];
            tile[cc][yy][xx] = v;
        }
        __syncthreads();
#pragma unroll
        for (int cc = 0; cc < 4; cc++) {
            float ctr = tile[cc][ty + 1][tx + 1];
#pragma unroll
            for (int t = 0; t < 9; t++) {
                float d = tile[cc][ty + t / 3][tx + t % 3] - ctr;
                acc[t] += d * d;
            }
        }
    }
    int p = (h0 + ty) * W + (w0 + tx);
#pragma unroll
    for (int t = 0; t < 9; t++)
        part[((size_t)(blockIdx.z * 9 + t)) * HW + p] = acc[t];
}

__global__ void kk_final_kernel(const float* __restrict__ part, float* __restrict__ kkout,
                                int HW, int nchunk) {
    int i = blockIdx.x * 256 + threadIdx.x;
    if (i >= 9 * HW) return;
    int t = i / HW, p = i - t * HW;
    float s = 0.f;
    for (int c = 0; c < nchunk; c++)
        s += part[((size_t)(c * 9 + t)) * HW + p];
    kkout[(size_t)t * HW + p] = __expf(-0.5f * s);
}

// ---------------- PAC combine ----------------
__global__ void pac_combine_kernel(const float* __restrict__ z, const float* __restrict__ kkb,
                                   const float* __restrict__ bias, float* __restrict__ out,
                                   int Ho, int Wo, int Hin, int Win, int woShift) {
    int o = blockIdx.y;
    int p = blockIdx.x * blockDim.x + threadIdx.x;
    int np = Ho * Wo;
    if (p >= np) return;
    int h = p >> woShift, w = p & (Wo - 1);
    int nsrc = Hin * Win;
    float s = bias[o];
#pragma unroll
    for (int i = 0; i < 3; i++) {
        int hi = h + i;
        if (!(hi & 1)) continue;
        int sh = (hi - 1) >> 1;
        if (sh >= Hin) continue;
#pragma unroll
        for (int j = 0; j < 3; j++) {
            int wj = w + j;
            if (!(wj & 1)) continue;
            int sw = (wj - 1) >> 1;
            if (sw >= Win) continue;
            int t = i * 3 + j;
            s += kkb[(size_t)t * np + p] * z[(size_t)(o * 9 + t) * nsrc + sh * Win + sw];
        }
    }
    out[(size_t)o * np + p] = s;
}

// ---------------- final 3x3 conv, 64 -> 3 channels, 256x256 ----------------
__global__ __launch_bounds__(256) void conv_out_kernel(const float* __restrict__ in,
                                                       const float* __restrict__ wgt,
                                                       const float* __restrict__ bias,
                                                       float* __restrict__ out) {
    __shared__ float ws[3 * 64 * 9];
    __shared__ float tile[8][18][18];
    const int H = 256, W = 256;
    for (int idx = threadIdx.x; idx < 1728; idx += 256) ws[idx] = wgt[idx];
    int tx = threadIdx.x & 15, ty = threadIdx.x >> 4;
    int w0 = blockIdx.x * 16, h0 = blockIdx.y * 16;
    float acc[3] = {bias[0], bias[1], bias[2]};
    for (int c0 = 0; c0 < 64; c0 += 8) {
        __syncthreads();
        for (int idx = threadIdx.x; idx < 8 * 324; idx += 256) {
            int cc = idx / 324, rem = idx % 324;
            int yy = rem / 18, xx = rem % 18;
            int gy = h0 + yy - 1, gx = w0 + xx - 1;
            float v = 0.f;
            if (gy >= 0 && gy < H && gx >= 0 && gx < W)
                v = in[(size_t)(c0 + cc) * H * W + gy * W + gx];
            tile[cc][yy][xx] = v;
        }
        __syncthreads();
#pragma unroll
        for (int cc = 0; cc < 8; cc++) {
            float v[9];
#pragma unroll
            for (int t = 0; t < 9; t++)
                v[t] = tile[cc][ty + t / 3][tx + t % 3];
#pragma unroll
            for (int o = 0; o < 3; o++)
#pragma unroll
                for (int t = 0; t < 9; t++)
                    acc[o] += v[t] * ws[(o * 64 + c0 + cc) * 9 + t];
        }
    }
    int p = (h0 + ty) * W + (w0 + tx);
#pragma unroll
    for (int o = 0; o < 3; o++) out[(size_t)o * H * W + p] = acc[o];
}

// ---------------- host ----------------
extern "C" void kernel_launch(void* const* d_in, const int* in_sizes, int n_in,
                              void* d_out, int out_size) {
    const float* x       = (const float*)d_in[0];
    const float* ef2     = (const float*)d_in[1];
    const float* ef1     = (const float*)d_in[2];
    const float* w_adj2  = (const float*)d_in[3];
    const float* b_adj2  = (const float*)d_in[4];
    const float* w_adj1  = (const float*)d_in[5];
    const float* b_adj1  = (const float*)d_in[6];
    const float* w_pac16 = (const float*)d_in[7];
    const float* b_pac16 = (const float*)d_in[8];
    const float* w_pac20 = (const float*)d_in[9];
    const float* b_pac20 = (const float*)d_in[10];
    const float* w_out   = (const float*)d_in[11];
    const float* b_out   = (const float*)d_in[12];
    float* out = (float*)d_out;

    float* S = nullptr;
    cudaGetSymbolAddress((void**)&S, g_scratch);
    float* xbuf0 = S + OFF_XBUF0;
    float* g2    = S + OFF_G2;
    float* kk1   = S + OFF_KK1;
    float* z1    = S + OFF_Z1;
    float* x1    = S + OFF_X1;
    float* g1    = S + OFF_G1;
    float* kk2   = S + OFF_KK2;
    float* z2    = S + OFF_Z2;
    float* x2    = S + OFF_X2;
    float* kp1   = S + OFF_KP1;
    float* kp2   = S + OFF_KP2;
    __nv_bfloat16* xsH = (__nv_bfloat16*)(S + OFF_XSH);
    __nv_bfloat16* xsL = (__nv_bfloat16*)(S + OFF_XSL);
    __nv_bfloat16* p2H = (__nv_bfloat16*)(S + OFF_P2H);
    __nv_bfloat16* p2L = (__nv_bfloat16*)(S + OFF_P2L);
    __nv_bfloat16* p1H = (__nv_bfloat16*)(S + OFF_P1H);
    __nv_bfloat16* p1L = (__nv_bfloat16*)(S + OFF_P1L);
    __nv_bfloat16* x1H = (__nv_bfloat16*)(S + OFF_X1H);
    __nv_bfloat16* x1L = (__nv_bfloat16*)(S + OFF_X1L);
    __nv_bfloat16* aw2   = (__nv_bfloat16*)(S + OFF_AW2);
    __nv_bfloat16* awp16 = (__nv_bfloat16*)(S + OFF_AWP16);
    __nv_bfloat16* aw1   = (__nv_bfloat16*)(S + OFF_AW1);
    __nv_bfloat16* awp20 = (__nv_bfloat16*)(S + OFF_AWP20);

    cudaFuncSetAttribute(gemm_as_kernel, cudaFuncAttributeMaxDynamicSharedMemorySize, SMEM_AS);

    // weight splits (independent of activations)
    wsplit_conv_kernel<<<(256 * 1152 + 255) / 256, 256>>>(w_adj2, aw2, 256, 128, 7);
    wsplit_pac_kernel<<<(1152 * 256 + 255) / 256, 256>>>(w_pac16, awp16, 128, 256);
    wsplit_conv_kernel<<<(128 * 576 + 255) / 256, 256>>>(w_adj1, aw1, 128, 64, 6);
    wsplit_pac_kernel<<<(576 * 128 + 255) / 256, 256>>>(w_pac20, awp20, 64, 128);

    // stage 0: double inorm on x (256 ch, 64x64) -> split to NHWC planes
    inorm2_kernel<<<256, 256>>>(x, xbuf0, 4096);
    split_kernel<<<dim3(128, 8), 256>>>(xbuf0, xsH, xsL, 256, 64, 64, 0);

    // guide conv g2 = conv3x3(ef_lv2; 128->256 @128x128)
    split_kernel<<<dim3((16900 + 31) / 32, 4), 256>>>(ef2, p2H, p2L, 128, 128, 128, 1);
    gemm_as_kernel<<<dim3(128, 2), 256, SMEM_AS>>>(aw2, p2H, p2L, b_adj2, g2,
                                                   256, 16384, 1152, 7, 130, 7);
    // PAC 16
    kk_partial_kernel<<<dim3(8, 8, 8), 256>>>(g2, kp1, 128, 128);
    kk_final_kernel<<<(9 * 16384 + 255) / 256, 256>>>(kp1, kk1, 16384, 8);
    gemm_as_kernel<<<dim3(32, 9), 256, SMEM_AS>>>(awp16, xsH, xsL, nullptr, z1,
                                                  1152, 4096, 256, 8, 4096, 12);
    pac_combine_kernel<<<dim3(64, 128), 256>>>(z1, kk1, b_pac16, x1, 128, 128, 64, 64, 7);
    inorm2_kernel<<<128, 256>>>(x1, x1, 16384);
    split_kernel<<<dim3(512, 4), 256>>>(x1, x1H, x1L, 128, 128, 128, 0);

    // guide conv g1 = conv3x3(ef_lv1; 64->128 @256x256)
    split_kernel<<<dim3((66564 + 31) / 32, 2), 256>>>(ef1, p1H, p1L, 64, 256, 256, 1);
    gemm_as_kernel<<<dim3(512, 1), 256, SMEM_AS>>>(aw1, p1H, p1L, b_adj1, g1,
                                                   128, 65536, 576, 6, 258, 8);
    // PAC 20
    kk_partial_kernel<<<dim3(16, 16, 4), 256>>>(g1, kp2, 256, 256);
    kk_final_kernel<<<(9 * 65536 + 255) / 256, 256>>>(kp2, kk2, 65536, 4);
    gemm_as_kernel<<<dim3(128, 5), 256, SMEM_AS>>>(awp20, x1H, x1L, nullptr, z2,
                                                   576, 16384, 128, 7, 16384, 14);
    pac_combine_kernel<<<dim3(256, 64), 256>>>(z2, kk2, b_pac20, x2, 256, 256, 128, 128, 8);
    inorm2_kernel<<<64, 256>>>(x2, x2, 65536);

    // final conv 64 -> 3
    conv_out_kernel<<<dim3(16, 16), 256>>>(x2, w_out, b_out, out);
}

// round 9
// speedup vs baseline: 1.7109x; 1.0534x over previous
#include <cuda_runtime.h>
#include <cuda_bf16.h>
#include <cstdint>

#define EPS 1e-5f

// ---------------- scratch layout (floats) ----------------
static const size_t OFF_XBUF0 = 0;           // 1,048,576
static const size_t OFF_G2    = 1048576;     // 4,194,304
static const size_t OFF_KK1   = 5242880;     // 147,456
static const size_t OFF_Z1    = 5390336;     // 4,718,592
static const size_t OFF_X1    = 10108928;    // 2,097,152
static const size_t OFF_G1    = 12206080;    // 8,388,608
static const size_t OFF_KK2   = 20594688;    // 589,824
static const size_t OFF_Z2    = 21184512;    // 9,437,184
static const size_t OFF_X2    = 30621696;    // 4,194,304
static const size_t OFF_KP1   = 34816000;    // 1,179,648
static const size_t OFF_KP2   = 35995648;    // 2,359,296
// bf16 regions (size in floats = elems/2)
static const size_t OFF_XSH   = 38354944;    // 524,288
static const size_t OFF_XSL   = 38879232;    // 524,288
static const size_t OFF_P2H   = 39403520;    // 1,081,600
static const size_t OFF_P2L   = 40485120;    // 1,081,600
static const size_t OFF_P1H   = 41566720;    // 2,130,048
static const size_t OFF_P1L   = 43696768;    // 2,130,048
static const size_t OFF_X1H   = 45826816;    // 1,048,576
static const size_t OFF_X1L   = 46875392;    // 1,048,576
static const size_t OFF_AW2   = 47923968;    // 442,368
static const size_t OFF_AWP16 = 48366336;    // 442,368
static const size_t OFF_AW1   = 48808704;    // 110,592
static const size_t OFF_AWP20 = 48919296;    // 122,880 (640 rows, padded, zero-backed)
static const size_t SCRATCH_FLOATS = 49042176; // ~196 MB

__device__ float g_scratch[SCRATCH_FLOATS];

// ================= helpers =================
__device__ __forceinline__ uint32_t smem_u32(const void* p) {
    uint32_t a;
    asm("{ .reg .u64 t; cvta.to.shared.u64 t, %1; cvt.u32.u64 %0, t; }" : "=r"(a) : "l"(p));
    return a;
}
__device__ __forceinline__ void cpasync16(uint32_t dst, const void* src) {
    asm volatile("cp.async.cg.shared.global [%0], [%1], 16;" :: "r"(dst), "l"(src));
}
__device__ __forceinline__ void cpcommit() {
    asm volatile("cp.async.commit_group;" ::: "memory");
}
__device__ __forceinline__ void ldmx4(uint32_t* r, uint32_t addr) {
    asm volatile("ldmatrix.sync.aligned.m8n8.x4.shared.b16 {%0,%1,%2,%3}, [%4];"
                 : "=r"(r[0]), "=r"(r[1]), "=r"(r[2]), "=r"(r[3]) : "r"(addr));
}
__device__ __forceinline__ void mma16816(float* d, const uint32_t* a, uint32_t b0, uint32_t b1) {
    asm volatile(
        "mma.sync.aligned.m16n8k16.row.col.f32.bf16.bf16.f32 "
        "{%0,%1,%2,%3}, {%4,%5,%6,%7}, {%8,%9}, {%0,%1,%2,%3};"
        : "+f"(d[0]), "+f"(d[1]), "+f"(d[2]), "+f"(d[3])
        : "r"(a[0]), "r"(a[1]), "r"(a[2]), "r"(a[3]), "r"(b0), "r"(b1));
}

// ================= async-pipelined HMMA GEMM (64k chunks, ldmatrix) =================
// C[m,p] = bias[m] + sum_{k'} Asp[m][k'] * Bplane(term)[(h+di)*Wp+(w+dj)][c]
// Asp: [mRows][3K] bf16 terms [hi|hi|lo].  B planes: NHWC bf16 hi/lo.
// chunk = 64 bf16 k; 3-stage cp.async pipeline; tile 128x128, 8 warps.
#define NSTAGE 3
#define ROWB 144                 // smem row stride bytes (128 data + 16 pad)
#define STG_B (2 * 128 * ROWB)   // 36864 per stage (A then B)
#define BOFFS (128 * ROWB)       // 18432: B region offset within stage
__global__ __launch_bounds__(256, 2) void gemm_as_kernel(
    const __nv_bfloat16* __restrict__ Ag, const __nv_bfloat16* __restrict__ Bhi,
    const __nv_bfloat16* __restrict__ Blo, const float* __restrict__ bias,
    float* __restrict__ C, int M, int N, int K, int cinShift, int Wp, int wShift)
{
    extern __shared__ char smem[];
    uint32_t sbase = smem_u32(smem);
    int tid = threadIdx.x, lane = tid & 31, wrp = tid >> 5;
    int wm = wrp & 3, wn = wrp >> 2;
    int m0 = blockIdx.y * 128, p0 = blockIdx.x * 128;
    int K3 = K * 3, nk = K >> 6, ncc = nk * 3;   // 64-k chunks per term
    int Cin = 1 << cinShift;

    // fill-thread coords: row (0..127), seg (0..1) -> 64B halves of 128B row
    int frow = tid & 127, fseg = tid >> 7;
    const char* arow = (const char*)(Ag + (size_t)(m0 + frow) * K3) + fseg * 64;
    int p = p0 + frow;
    int h = p >> wShift, w = p & ((1 << wShift) - 1);
    size_t bOff = (size_t)(h * Wp + w) * Cin + fseg * 32;   // elems
    uint32_t dA = frow * ROWB + fseg * 64;
    uint32_t dB = dA + BOFFS;

    // ldmatrix per-lane offsets
    int l7 = lane & 7, l8 = (lane >> 3) & 1, l16 = (lane >> 4) & 1;
    uint32_t aOff0 = (uint32_t)((wm * 32 + l7 + l8 * 8) * ROWB + l16 * 16);
    uint32_t aOff1 = aOff0 + 16 * ROWB;
    uint32_t bOffL[4];
#pragma unroll
    for (int nt2 = 0; nt2 < 4; nt2++)
        bOffL[nt2] = (uint32_t)(BOFFS + (wn * 64 + nt2 * 16 + l7 + l16 * 8) * ROWB + l8 * 16);

    float acc[2][8][4] = {};

    auto issue = [&](int cc) {
        int stg = cc % NSTAGE;
        int term = (cc >= 2 * nk) ? 2 : (cc >= nk ? 1 : 0);
        int kk = (cc - term * nk) << 6;
        const char* As = arow + (size_t)(term * K + kk) * 2;
        uint32_t da = sbase + stg * STG_B + dA;
#pragma unroll
        for (int i = 0; i < 4; i++) cpasync16(da + i * 16, As + i * 16);
        int tap = kk >> cinShift;
        int c0 = kk & (Cin - 1);
        int di = (tap >= 6) ? 2 : (tap >= 3 ? 1 : 0);
        int dj = tap - di * 3;
        const __nv_bfloat16* plane = (term == 1) ? Blo : Bhi;
        const char* Bs = (const char*)(plane + bOff + (size_t)(di * Wp + dj) * Cin + c0);
        uint32_t db = sbase + stg * STG_B + dB;
#pragma unroll
        for (int i = 0; i < 4; i++) cpasync16(db + i * 16, Bs + i * 16);
        cpcommit();
    };

    issue(0);
    issue(1);

    for (int cc = 0; cc < ncc; cc++) {
        asm volatile("cp.async.wait_group 1;" ::: "memory");
        __syncthreads();
        uint32_t sb = sbase + (cc % NSTAGE) * STG_B;
#pragma unroll
        for (int ks = 0; ks < 4; ks++) {
            uint32_t kofs = ks * 32;
            uint32_t a0[4], a1[4];
            ldmx4(a0, sb + aOff0 + kofs);
            ldmx4(a1, sb + aOff1 + kofs);
#pragma unroll
            for (int nt2 = 0; nt2 < 4; nt2++) {
                uint32_t b[4];
                ldmx4(b, sb + bOffL[nt2] + kofs);
                mma16816(acc[0][nt2 * 2],     a0, b[0], b[1]);
                mma16816(acc[1][nt2 * 2],     a1, b[0], b[1]);
                mma16816(acc[0][nt2 * 2 + 1], a0, b[2], b[3]);
                mma16816(acc[1][nt2 * 2 + 1], a1, b[2], b[3]);
            }
        }
        int nx = cc + 2;
        if (nx < ncc) issue(nx); else cpcommit();
    }

    // epilogue: registers -> C
    int r = lane >> 2, cp2 = (lane & 3) * 2;
#pragma unroll
    for (int mt = 0; mt < 2; mt++) {
        int mA = m0 + wm * 32 + mt * 16 + r;
        int mB = mA + 8;
        float bvA = (bias && mA < M) ? bias[mA] : 0.f;
        float bvB = (bias && mB < M) ? bias[mB] : 0.f;
#pragma unroll
        for (int nt = 0; nt < 8; nt++) {
            int n = p0 + wn * 64 + nt * 8 + cp2;
            if (mA < M)
                *(float2*)(C + (size_t)mA * N + n) =
                    make_float2(acc[mt][nt][0] + bvA, acc[mt][nt][1] + bvA);
            if (mB < M)
                *(float2*)(C + (size_t)mB * N + n) =
                    make_float2(acc[mt][nt][2] + bvB, acc[mt][nt][3] + bvB);
        }
    }
}
static const int SMEM_AS = NSTAGE * STG_B;  // 110592

// ---------------- NCHW float -> NHWC(padded) bf16 hi/lo, smem transpose ----------------
__global__ __launch_bounds__(256) void split_kernel(const float* __restrict__ in,
                                                    __nv_bfloat16* __restrict__ outH,
                                                    __nv_bfloat16* __restrict__ outL,
                                                    int C, int H, int W, int pad) {
    int Wp = W + 2 * pad, Hp = H + 2 * pad, Np = Hp * Wp;
    __shared__ float t[32][33];
    int p0 = blockIdx.x * 32, c0 = blockIdx.y * 32;
    int tx = threadIdx.x & 31, ty = threadIdx.x >> 5;   // 32 x 8
#pragma unroll
    for (int i = 0; i < 4; i++) {
        int c = c0 + ty + i * 8;
        int pos = p0 + tx;
        float v = 0.f;
        if (pos < Np) {
            int py = pos / Wp, px = pos - py * Wp;
            int iy = py - pad, ix = px - pad;
            if (iy >= 0 && iy < H && ix >= 0 && ix < W)
                v = in[((size_t)c * H + iy) * W + ix];
        }
        t[ty + i * 8][tx] = v;
    }
    __syncthreads();
#pragma unroll
    for (int i = 0; i < 4; i++) {
        int pos = p0 + ty + i * 8;
        int c = c0 + tx;
        if (pos < Np) {
            float v = t[tx][ty + i * 8];
            __nv_bfloat16 hb = __float2bfloat16(v);
            outH[(size_t)pos * C + c] = hb;
            outL[(size_t)pos * C + c] = __float2bfloat16(v - __bfloat162float(hb));
        }
    }
}

// ---------------- weight split: conv (O,Cin,3,3) -> Asp[m=o][3K], k = tap*Cin+c ----------------
__global__ void wsplit_conv_kernel(const float* __restrict__ w, __nv_bfloat16* __restrict__ out,
                                   int O, int Cin, int cinShift) {
    int K = 9 * Cin, K3 = 3 * K;
    int idx = blockIdx.x * 256 + threadIdx.x;
    if (idx >= O * K) return;
    int m = idx / K, k = idx - m * K;
    int c = k & (Cin - 1), t = k >> cinShift;
    float v = w[((size_t)m * Cin + c) * 9 + t];
    __nv_bfloat16 hb = __float2bfloat16(v);
    __nv_bfloat16 lb = __float2bfloat16(v - __bfloat162float(hb));
    out[(size_t)m * K3 + k] = hb;
    out[(size_t)m * K3 + K + k] = hb;
    out[(size_t)m * K3 + 2 * K + k] = lb;
}

// ---------------- weight split: pac (Cin,OC,3,3) -> Asp[m=o*9+t][3K], k = c ----------------
__global__ void wsplit_pac_kernel(const float* __restrict__ w, __nv_bfloat16* __restrict__ out,
                                  int OC, int Cin) {
    int M = OC * 9, K = Cin, K3 = 3 * K;
    int idx = blockIdx.x * 256 + threadIdx.x;
    if (idx >= M * K) return;
    int m = idx / K, k = idx - m * K;
    int o = m / 9, t = m - o * 9;
    float v = w[((size_t)k * OC + o) * 9 + t];
    __nv_bfloat16 hb = __float2bfloat16(v);
    __nv_bfloat16 lb = __float2bfloat16(v - __bfloat162float(hb));
    out[(size_t)m * K3 + k] = hb;
    out[(size_t)m * K3 + K + k] = hb;
    out[(size_t)m * K3 + 2 * K + k] = lb;
}

// ---------------- fused double instance-norm + residual (x2), float4 ----------------
__global__ __launch_bounds__(256) void inorm2_kernel(const float* __restrict__ in,
                                                     float* __restrict__ out, int HW) {
    int c = blockIdx.x;
    const float4* x4 = (const float4*)(in + (size_t)c * HW);
    float4* y4 = (float4*)(out + (size_t)c * HW);
    int n4 = HW >> 2;
    float s = 0.f, s2 = 0.f;
    for (int i = threadIdx.x; i < n4; i += 256) {
        float4 v = x4[i];
        s += v.x + v.y + v.z + v.w;
        s2 += v.x * v.x + v.y * v.y + v.z * v.z + v.w * v.w;
    }
    __shared__ float rs[256], rq[256];
    rs[threadIdx.x] = s; rq[threadIdx.x] = s2;
    __syncthreads();
    for (int o = 128; o > 0; o >>= 1) {
        if (threadIdx.x < o) { rs[threadIdx.x] += rs[threadIdx.x + o]; rq[threadIdx.x] += rq[threadIdx.x + o]; }
        __syncthreads();
    }
    float m = rs[0] / (float)HW;
    float v = rq[0] / (float)HW - m * m;
    if (v < 0.f) v = 0.f;
    float a = 1.f + rsqrtf(v + EPS);
    float scale = a * (1.f + rsqrtf(v * a * a + EPS));
    for (int i = threadIdx.x; i < n4; i += 256) {
        float4 t = x4[i];
        t.x = m + (t.x - m) * scale;
        t.y = m + (t.y - m) * scale;
        t.z = m + (t.z - m) * scale;
        t.w = m + (t.w - m) * scale;
        y4[i] = t;
    }
}

// ---------------- kk partial ----------------
__global__ __launch_bounds__(256) void kk_partial_kernel(const float* __restrict__ g,
                                                         float* __restrict__ part,
                                                         int H, int W) {
    __shared__ float tile[4][18][18];
    int tx = threadIdx.x & 15, ty = threadIdx.x >> 4;
    int w0 = blockIdx.x * 16, h0 = blockIdx.y * 16;
    int HW = H * W;
    float acc[9] = {};
    int cbase = blockIdx.z * 32;
    for (int c0 = cbase; c0 < cbase + 32; c0 += 4) {
        __syncthreads();
        for (int idx = threadIdx.x; idx < 4 * 324; idx += 256) {
            int cc = idx / 324, rem = idx % 324;
            int yy = rem / 18, xx = rem % 18;
            int gy = h0 + yy - 1, gx = w0 + xx - 1;
            float v = 0.f;
            if (gy >= 0 && gy < H && gx >= 0 && gx < W)
                v = g[(size_t)(c0 + cc) * HW + gy * W + gx];
            tile[cc][yy][xx] = v;
        }
        __syncthreads();
#pragma unroll
        for (int cc = 0; cc < 4; cc++) {
            float ctr = tile[cc][ty + 1][tx + 1];
#pragma unroll
            for (int t = 0; t < 9; t++) {
                float d = tile[cc][ty + t / 3][tx + t % 3] - ctr;
                acc[t] += d * d;
            }
        }
    }
    int p = (h0 + ty) * W + (w0 + tx);
#pragma unroll
    for (int t = 0; t < 9; t++)
        part[((size_t)(blockIdx.z * 9 + t)) * HW + p] = acc[t];
}

__global__ void kk_final_kernel(const float* __restrict__ part, float* __restrict__ kkout,
                                int HW, int nchunk) {
    int i = blockIdx.x * 256 + threadIdx.x;
    if (i >= 9 * HW) return;
    int t = i / HW, p = i - t * HW;
    float s = 0.f;
    for (int c = 0; c < nchunk; c++)
        s += part[((size_t)(c * 9 + t)) * HW + p];
    kkout[(size_t)t * HW + p] = __expf(-0.5f * s);
}

// ---------------- PAC combine ----------------
__global__ void pac_combine_kernel(const float* __restrict__ z, const float* __restrict__ kkb,
                                   const float* __restrict__ bias, float* __restrict__ out,
                                   int Ho, int Wo, int Hin, int Win, int woShift) {
    int o = blockIdx.y;
    int p = blockIdx.x * blockDim.x + threadIdx.x;
    int np = Ho * Wo;
    if (p >= np) return;
    int h = p >> woShift, w = p & (Wo - 1);
    int nsrc = Hin * Win;
    float s = bias[o];
#pragma unroll
    for (int i = 0; i < 3; i++) {
        int hi = h + i;
        if (!(hi & 1)) continue;
        int sh = (hi - 1) >> 1;
        if (sh >= Hin) continue;
#pragma unroll
        for (int j = 0; j < 3; j++) {
            int wj = w + j;
            if (!(wj & 1)) continue;
            int sw = (wj - 1) >> 1;
            if (sw >= Win) continue;
            int t = i * 3 + j;
            s += kkb[(size_t)t * np + p] * z[(size_t)(o * 9 + t) * nsrc + sh * Win + sw];
        }
    }
    out[(size_t)o * np + p] = s;
}

// ---------------- final 3x3 conv, 64 -> 3 channels, 256x256 ----------------
__global__ __launch_bounds__(256) void conv_out_kernel(const float* __restrict__ in,
                                                       const float* __restrict__ wgt,
                                                       const float* __restrict__ bias,
                                                       float* __restrict__ out) {
    __shared__ float ws[3 * 64 * 9];
    __shared__ float tile[8][18][18];
    const int H = 256, W = 256;
    for (int idx = threadIdx.x; idx < 1728; idx += 256) ws[idx] = wgt[idx];
    int tx = threadIdx.x & 15, ty = threadIdx.x >> 4;
    int w0 = blockIdx.x * 16, h0 = blockIdx.y * 16;
    float acc[3] = {bias[0], bias[1], bias[2]};
    for (int c0 = 0; c0 < 64; c0 += 8) {
        __syncthreads();
        for (int idx = threadIdx.x; idx < 8 * 324; idx += 256) {
            int cc = idx / 324, rem = idx % 324;
            int yy = rem / 18, xx = rem % 18;
            int gy = h0 + yy - 1, gx = w0 + xx - 1;
            float v = 0.f;
            if (gy >= 0 && gy < H && gx >= 0 && gx < W)
                v = in[(size_t)(c0 + cc) * H * W + gy * W + gx];
            tile[cc][yy][xx] = v;
        }
        __syncthreads();
#pragma unroll
        for (int cc = 0; cc < 8; cc++) {
            float v[9];
#pragma unroll
            for (int t = 0; t < 9; t++)
                v[t] = tile[cc][ty + t / 3][tx + t % 3];
#pragma unroll
            for (int o = 0; o < 3; o++)
#pragma unroll
                for (int t = 0; t < 9; t++)
                    acc[o] += v[t] * ws[(o * 64 + c0 + cc) * 9 + t];
        }
    }
    int p = (h0 + ty) * W + (w0 + tx);
#pragma unroll
    for (int o = 0; o < 3; o++) out[(size_t)o * H * W + p] = acc[o];
}

// ---------------- host ----------------
extern "C" void kernel_launch(void* const* d_in, const int* in_sizes, int n_in,
                              void* d_out, int out_size) {
    const float* x       = (const float*)d_in[0];
    const float* ef2     = (const float*)d_in[1];
    const float* ef1     = (const float*)d_in[2];
    const float* w_adj2  = (const float*)d_in[3];
    const float* b_adj2  = (const float*)d_in[4];
    const float* w_adj1  = (const float*)d_in[5];
    const float* b_adj1  = (const float*)d_in[6];
    const float* w_pac16 = (const float*)d_in[7];
    const float* b_pac16 = (const float*)d_in[8];
    const float* w_pac20 = (const float*)d_in[9];
    const float* b_pac20 = (const float*)d_in[10];
    const float* w_out   = (const float*)d_in[11];
    const float* b_out   = (const float*)d_in[12];
    float* out = (float*)d_out;

    float* S = nullptr;
    cudaGetSymbolAddress((void**)&S, g_scratch);
    float* xbuf0 = S + OFF_XBUF0;
    float* g2    = S + OFF_G2;
    float* kk1   = S + OFF_KK1;
    float* z1    = S + OFF_Z1;
    float* x1    = S + OFF_X1;
    float* g1    = S + OFF_G1;
    float* kk2   = S + OFF_KK2;
    float* z2    = S + OFF_Z2;
    float* x2    = S + OFF_X2;
    float* kp1   = S + OFF_KP1;
    float* kp2   = S + OFF_KP2;
    __nv_bfloat16* xsH = (__nv_bfloat16*)(S + OFF_XSH);
    __nv_bfloat16* xsL = (__nv_bfloat16*)(S + OFF_XSL);
    __nv_bfloat16* p2H = (__nv_bfloat16*)(S + OFF_P2H);
    __nv_bfloat16* p2L = (__nv_bfloat16*)(S + OFF_P2L);
    __nv_bfloat16* p1H = (__nv_bfloat16*)(S + OFF_P1H);
    __nv_bfloat16* p1L = (__nv_bfloat16*)(S + OFF_P1L);
    __nv_bfloat16* x1H = (__nv_bfloat16*)(S + OFF_X1H);
    __nv_bfloat16* x1L = (__nv_bfloat16*)(S + OFF_X1L);
    __nv_bfloat16* aw2   = (__nv_bfloat16*)(S + OFF_AW2);
    __nv_bfloat16* awp16 = (__nv_bfloat16*)(S + OFF_AWP16);
    __nv_bfloat16* aw1   = (__nv_bfloat16*)(S + OFF_AW1);
    __nv_bfloat16* awp20 = (__nv_bfloat16*)(S + OFF_AWP20);

    cudaFuncSetAttribute(gemm_as_kernel, cudaFuncAttributeMaxDynamicSharedMemorySize, SMEM_AS);

    // weight splits (independent of activations)
    wsplit_conv_kernel<<<(256 * 1152 + 255) / 256, 256>>>(w_adj2, aw2, 256, 128, 7);
    wsplit_pac_kernel<<<(1152 * 256 + 255) / 256, 256>>>(w_pac16, awp16, 128, 256);
    wsplit_conv_kernel<<<(128 * 576 + 255) / 256, 256>>>(w_adj1, aw1, 128, 64, 6);
    wsplit_pac_kernel<<<(576 * 128 + 255) / 256, 256>>>(w_pac20, awp20, 64, 128);

    // stage 0: double inorm on x (256 ch, 64x64) -> split to NHWC planes
    inorm2_kernel<<<256, 256>>>(x, xbuf0, 4096);
    split_kernel<<<dim3(128, 8), 256>>>(xbuf0, xsH, xsL, 256, 64, 64, 0);

    // guide conv g2 = conv3x3(ef_lv2; 128->256 @128x128)
    split_kernel<<<dim3((16900 + 31) / 32, 4), 256>>>(ef2, p2H, p2L, 128, 128, 128, 1);
    gemm_as_kernel<<<dim3(128, 2), 256, SMEM_AS>>>(aw2, p2H, p2L, b_adj2, g2,
                                                   256, 16384, 1152, 7, 130, 7);
    // PAC 16
    kk_partial_kernel<<<dim3(8, 8, 8), 256>>>(g2, kp1, 128, 128);
    kk_final_kernel<<<(9 * 16384 + 255) / 256, 256>>>(kp1, kk1, 16384, 8);
    gemm_as_kernel<<<dim3(32, 9), 256, SMEM_AS>>>(awp16, xsH, xsL, nullptr, z1,
                                                  1152, 4096, 256, 8, 4096, 12);
    pac_combine_kernel<<<dim3(64, 128), 256>>>(z1, kk1, b_pac16, x1, 128, 128, 64, 64, 7);
    inorm2_kernel<<<128, 256>>>(x1, x1, 16384);
    split_kernel<<<dim3(512, 4), 256>>>(x1, x1H, x1L, 128, 128, 128, 0);

    // guide conv g1 = conv3x3(ef_lv1; 64->128 @256x256)
    split_kernel<<<dim3((66564 + 31) / 32, 2), 256>>>(ef1, p1H, p1L, 64, 256, 256, 1);
    gemm_as_kernel<<<dim3(512, 1), 256, SMEM_AS>>>(aw1, p1H, p1L, b_adj1, g1,
                                                   128, 65536, 576, 6, 258, 8);
    // PAC 20
    kk_partial_kernel<<<dim3(16, 16, 4), 256>>>(g1, kp2, 256, 256);
    kk_final_kernel<<<(9 * 65536 + 255) / 256, 256>>>(kp2, kk2, 65536, 4);
    gemm_as_kernel<<<dim3(128, 5), 256, SMEM_AS>>>(awp20, x1H, x1L, nullptr, z2,
                                                   576, 16384, 128, 7, 16384, 14);
    pac_combine_kernel<<<dim3(256, 64), 256>>>(z2, kk2, b_pac20, x2, 256, 256, 128, 128, 8);
    inorm2_kernel<<<64, 256>>>(x2, x2, 65536);

    // final conv 64 -> 3
    conv_out_kernel<<<dim3(16, 16), 256>>>(x2, w_out, b_out, out);
}